// round 5
// baseline (speedup 1.0000x reference)
#include <cuda_runtime.h>

#define N_NODES 100000
#define N_EDGES 1600000
#define D 128
#define H 8
#define DH 16
#define DFF 256
#define CAP 96          // max in-degree capacity (Poisson mean 16; P(>96) ~ 0)

// ---------------- scratch (device globals; no allocation allowed) ----------
__device__ float g_Q[N_NODES * D];
__device__ float g_KV[(long)N_NODES * 2 * D];   // [node][K 0..127 | V 128..255]
__device__ float g_wV[N_NODES * D];
__device__ float g_z[N_NODES * H];
__device__ int   g_cnt[N_NODES];
__device__ int   g_csr[(long)N_NODES * CAP];

// k-pair interleaved weights: Wi[k2*C + c] = (W[2k2][c], W[2k2+1][c])
__device__ float2 g_Wqi[64 * D];
__device__ float2 g_Wki[64 * D];
__device__ float2 g_Wvi[64 * D];
__device__ float2 g_Woi[64 * D];
__device__ float2 g_W1i[64 * DFF];
__device__ float2 g_W2i[128 * D];

// ---------------- packed f32x2 helpers -------------------------------------
typedef unsigned long long u64;

__device__ __forceinline__ u64 ffma2(u64 a, u64 b, u64 c) {
    u64 d;
    asm("fma.rn.f32x2 %0, %1, %2, %3;" : "=l"(d) : "l"(a), "l"(b), "l"(c));
    return d;
}
union U2 { u64 p; float2 f; };
__device__ __forceinline__ float hsum2(u64 a) { U2 u; u.p = a; return u.f.x + u.f.y; }

// ---------------- interleave weights ---------------------------------------
__global__ void interleave_kernel(
    const float* __restrict__ Wq, const float* __restrict__ Wk,
    const float* __restrict__ Wv, const float* __restrict__ Wo,
    const float* __restrict__ W1, const float* __restrict__ W2)
{
    int m = blockIdx.y;
    const float* W; float2* O; int C, tot;
    switch (m) {
        case 0: W = Wq; O = g_Wqi; C = D;   tot = 64 * D;   break;
        case 1: W = Wk; O = g_Wki; C = D;   tot = 64 * D;   break;
        case 2: W = Wv; O = g_Wvi; C = D;   tot = 64 * D;   break;
        case 3: W = Wo; O = g_Woi; C = D;   tot = 64 * D;   break;
        case 4: W = W1; O = g_W1i; C = DFF; tot = 64 * DFF; break;
        default:W = W2; O = g_W2i; C = D;   tot = 128 * D;  break;
    }
    int idx = blockIdx.x * 256 + threadIdx.x;
    if (idx >= tot) return;
    int k2 = idx / C, c = idx % C;
    O[idx] = make_float2(W[(2 * k2) * C + c], W[(2 * k2 + 1) * C + c]);
}

// ---------------- zero in-degree counters ----------------------------------
__global__ void zero_cnt_kernel() {
    int i = blockIdx.x * blockDim.x + threadIdx.x;
    if (i < N_NODES) g_cnt[i] = 0;
}

// ---------------- bucket edges by dst --------------------------------------
__global__ __launch_bounds__(256) void scatter_kernel(
    const int* __restrict__ src, const int* __restrict__ dst)
{
    int e = blockIdx.x * 256 + threadIdx.x;
    if (e >= N_EDGES) return;
    int d = dst[e];
    int pos = atomicAdd(&g_cnt[d], 1);
    if (pos < CAP) g_csr[(long)d * CAP + pos] = src[e];
}

// ---------------- QKV projection: k-packed FFMA2, 8 nodes x 4 cols ---------
// grid = (1563, 3). 256 threads, 64-node tile. Per k2: 8 LDS.64 + 2 LDG.128
// + 32 FFMA2 (no dup movs).
__global__ __launch_bounds__(256, 3) void qkv_kernel(const float* __restrict__ h)
{
    __shared__ float hs[64 * D];          // 32KB
    int t = threadIdx.x;
    int n0 = blockIdx.x * 64;
    int wsel = blockIdx.y;

    for (int i = t; i < 64 * (D / 4); i += 256) {
        int n = i / (D / 4);
        float4 v = make_float4(0.f, 0.f, 0.f, 0.f);
        if (n0 + n < N_NODES)
            v = ((const float4*)h)[(long)(n0 + n) * (D / 4) + (i % (D / 4))];
        ((float4*)hs)[i] = v;
    }
    __syncthreads();

    const u64* __restrict__ Wi = (const u64*)((wsel == 0) ? g_Wqi
                                : (wsel == 1) ? g_Wki : g_Wvi);

    int col4 = (t & 31) * 4;
    int nb   = (t >> 5) * 8;

    u64 acc2[8][4];
#pragma unroll
    for (int i = 0; i < 8; i++)
#pragma unroll
        for (int c = 0; c < 4; c++) acc2[i][c] = 0ull;

#pragma unroll 4
    for (int k2 = 0; k2 < 64; k2++) {
        ulonglong2 wA = *(const ulonglong2*)&Wi[k2 * D + col4];
        ulonglong2 wB = *(const ulonglong2*)&Wi[k2 * D + col4 + 2];
#pragma unroll
        for (int i = 0; i < 8; i++) {
            u64 hp = *(const u64*)&hs[(nb + i) * D + k2 * 2];
            acc2[i][0] = ffma2(hp, wA.x, acc2[i][0]);
            acc2[i][1] = ffma2(hp, wA.y, acc2[i][1]);
            acc2[i][2] = ffma2(hp, wB.x, acc2[i][2]);
            acc2[i][3] = ffma2(hp, wB.y, acc2[i][3]);
        }
    }

    float* O = (wsel == 0) ? g_Q : (wsel == 1) ? g_KV : g_KV + D;
    long rowstride = (wsel == 0) ? D : 2 * D;
#pragma unroll
    for (int i = 0; i < 8; i++) {
        int n = n0 + nb + i;
        if (n < N_NODES) {
            float4 r;
            r.x = hsum2(acc2[i][0]); r.y = hsum2(acc2[i][1]);
            r.z = hsum2(acc2[i][2]); r.w = hsum2(acc2[i][3]);
            *(float4*)&O[(long)n * rowstride + col4] = r;
        }
    }
}

// ---------------- aggregation: one warp per dst node (R3 version) ----------
__global__ __launch_bounds__(256) void agg_kernel()
{
    int n = blockIdx.x * 8 + (threadIdx.x >> 5);
    int lane = threadIdx.x & 31;

    float4 q = *(const float4*)&g_Q[(long)n * D + lane * 4];
    float4 acc = make_float4(0.f, 0.f, 0.f, 0.f);
    float accz = 0.f;

    int deg = g_cnt[n];
    if (deg > CAP) deg = CAP;
    const int* __restrict__ lst = &g_csr[(long)n * CAP];

    if (deg > 0) {
        int s = lst[0];
        const float* kvp = &g_KV[(long)s * 2 * D];
        float4 k = *(const float4*)&kvp[lane * 4];
        float4 v = *(const float4*)&kvp[D + lane * 4];
        for (int j = 0; j < deg; j++) {
            float4 kc = k, vc = v;
            if (j + 1 < deg) {
                int s2 = lst[j + 1];
                const float* kvp2 = &g_KV[(long)s2 * 2 * D];
                k = *(const float4*)&kvp2[lane * 4];
                v = *(const float4*)&kvp2[D + lane * 4];
            }
            float ps = kc.x * q.x + kc.y * q.y + kc.z * q.z + kc.w * q.w;
            ps += __shfl_xor_sync(0xffffffff, ps, 1);
            ps += __shfl_xor_sync(0xffffffff, ps, 2);
            float sc = __expf(fminf(fmaxf(ps * 0.25f, -5.f), 5.f));
            acc.x += sc * vc.x; acc.y += sc * vc.y;
            acc.z += sc * vc.z; acc.w += sc * vc.w;
            accz += sc;
        }
    }

    *(float4*)&g_wV[(long)n * D + lane * 4] = acc;
    if ((lane & 3) == 0) g_z[(long)n * H + (lane >> 2)] = accz;
}

// ---------------- epilogue: attn-norm + Wo + LN1 + FFN + LN2 ---------------
__device__ __forceinline__ void warp_ln4(float* buf, const float* __restrict__ g,
                                         const float* __restrict__ b,
                                         float* outbase, int t)
{
    int w = t >> 5, lane = t & 31;
    float4 gv = *(const float4*)&g[lane * 4];
    float4 bv = *(const float4*)&b[lane * 4];
#pragma unroll
    for (int i = 0; i < 4; i++) {
        int n = w * 4 + i;
        float4 v = *(float4*)&buf[n * D + lane * 4];
        float s  = v.x + v.y + v.z + v.w;
        float sq = v.x * v.x + v.y * v.y + v.z * v.z + v.w * v.w;
#pragma unroll
        for (int off = 16; off >= 1; off >>= 1) {
            s  += __shfl_xor_sync(0xffffffff, s, off);
            sq += __shfl_xor_sync(0xffffffff, sq, off);
        }
        float mu  = s * (1.f / D);
        float var = sq * (1.f / D) - mu * mu;
        float rs  = rsqrtf(var + 1e-5f);
        float4 o;
        o.x = (v.x - mu) * rs * gv.x + bv.x;
        o.y = (v.y - mu) * rs * gv.y + bv.y;
        o.z = (v.z - mu) * rs * gv.z + bv.z;
        o.w = (v.w - mu) * rs * gv.w + bv.w;
        *(float4*)&outbase[n * D + lane * 4] = o;
    }
}

// Block: 256 threads, 32-node tile. GEMM layout: 4 nodes x 4 cols k-packed.
__global__ __launch_bounds__(256) void epi_kernel(
    const float* __restrict__ h,
    const float* __restrict__ bo,
    const float* __restrict__ ln1g, const float* __restrict__ ln1b,
    const float* __restrict__ b1,
    const float* __restrict__ b2,
    const float* __restrict__ ln2g, const float* __restrict__ ln2b,
    float* __restrict__ out)
{
    __shared__ float sm[12288];           // 48KB
    float* XS = sm;                       // [32][128]
    float* A  = sm + 4096;                // [32][128]; later reused as FS
    float* FS = sm + 4096;                // [32][256]

    int t = threadIdx.x;
    int n0 = blockIdx.x * 32;

    // step 1: h_attn = wV / (z + eps)
    {
        int nl = t >> 3;
        int head = t & 7;
        int gn = n0 + nl;
        float inv = 1.f / (g_z[(long)gn * H + head] + 1e-6f);
        const float4* s4 = (const float4*)&g_wV[(long)gn * D + head * 16];
        float4* a4 = (float4*)&A[nl * D + head * 16];
#pragma unroll
        for (int j = 0; j < 4; j++) {
            float4 v = s4[j];
            v.x *= inv; v.y *= inv; v.z *= inv; v.w *= inv;
            a4[j] = v;
        }
    }
    __syncthreads();

    int col4 = (t & 31) * 4;
    int nb4  = (t >> 5) * 4;

    // step 2: XS = h + A @ Wo + bo
    {
        const u64* __restrict__ Wi = (const u64*)g_Woi;
        u64 acc2[4][4];
#pragma unroll
        for (int i = 0; i < 4; i++)
#pragma unroll
            for (int c = 0; c < 4; c++) acc2[i][c] = 0ull;
#pragma unroll 4
        for (int k2 = 0; k2 < 64; k2++) {
            ulonglong2 wA = *(const ulonglong2*)&Wi[k2 * D + col4];
            ulonglong2 wB = *(const ulonglong2*)&Wi[k2 * D + col4 + 2];
#pragma unroll
            for (int i = 0; i < 4; i++) {
                u64 hp = *(const u64*)&A[(nb4 + i) * D + k2 * 2];
                acc2[i][0] = ffma2(hp, wA.x, acc2[i][0]);
                acc2[i][1] = ffma2(hp, wA.y, acc2[i][1]);
                acc2[i][2] = ffma2(hp, wB.x, acc2[i][2]);
                acc2[i][3] = ffma2(hp, wB.y, acc2[i][3]);
            }
        }
        float4 bov = *(const float4*)&bo[col4];
        __syncthreads();   // all A reads done before any later reuse
#pragma unroll
        for (int i = 0; i < 4; i++) {
            float4 hv = *(const float4*)&h[(long)(n0 + nb4 + i) * D + col4];
            float4 x;
            x.x = hv.x + hsum2(acc2[i][0]) + bov.x;
            x.y = hv.y + hsum2(acc2[i][1]) + bov.y;
            x.z = hv.z + hsum2(acc2[i][2]) + bov.z;
            x.w = hv.w + hsum2(acc2[i][3]) + bov.w;
            *(float4*)&XS[(nb4 + i) * D + col4] = x;
        }
    }
    __syncthreads();

    // step 3: LN1 in place on XS
    warp_ln4(XS, ln1g, ln1b, XS, t);
    __syncthreads();

    // step 4: FS = relu(XS @ W1 + b1), two column halves of DFF=256.
    // FS rows nb4..nb4+3 are written entirely by this thread's warp.
    {
        const u64* __restrict__ Wi = (const u64*)g_W1i;
#pragma unroll
        for (int cc = 0; cc < DFF; cc += 128) {
            int c4 = cc + col4;
            u64 acc2[4][4];
#pragma unroll
            for (int i = 0; i < 4; i++)
#pragma unroll
                for (int c = 0; c < 4; c++) acc2[i][c] = 0ull;
#pragma unroll 4
            for (int k2 = 0; k2 < 64; k2++) {
                ulonglong2 wA = *(const ulonglong2*)&Wi[k2 * DFF + c4];
                ulonglong2 wB = *(const ulonglong2*)&Wi[k2 * DFF + c4 + 2];
#pragma unroll
                for (int i = 0; i < 4; i++) {
                    u64 hp = *(const u64*)&XS[(nb4 + i) * D + k2 * 2];
                    acc2[i][0] = ffma2(hp, wA.x, acc2[i][0]);
                    acc2[i][1] = ffma2(hp, wA.y, acc2[i][1]);
                    acc2[i][2] = ffma2(hp, wB.x, acc2[i][2]);
                    acc2[i][3] = ffma2(hp, wB.y, acc2[i][3]);
                }
            }
            float4 b1v = *(const float4*)&b1[c4];
#pragma unroll
            for (int i = 0; i < 4; i++) {
                float4 f;
                f.x = fmaxf(hsum2(acc2[i][0]) + b1v.x, 0.f);
                f.y = fmaxf(hsum2(acc2[i][1]) + b1v.y, 0.f);
                f.z = fmaxf(hsum2(acc2[i][2]) + b1v.z, 0.f);
                f.w = fmaxf(hsum2(acc2[i][3]) + b1v.w, 0.f);
                *(float4*)&FS[(nb4 + i) * DFF + c4] = f;
            }
        }
    }
    __syncthreads();

    // step 5: pre-LN2 = XS + FS @ W2 + b2   (k over 256)
    {
        const u64* __restrict__ Wi = (const u64*)g_W2i;
        u64 acc2[4][4];
#pragma unroll
        for (int i = 0; i < 4; i++)
#pragma unroll
            for (int c = 0; c < 4; c++) acc2[i][c] = 0ull;
#pragma unroll 4
        for (int k2 = 0; k2 < 128; k2++) {
            ulonglong2 wA = *(const ulonglong2*)&Wi[k2 * D + col4];
            ulonglong2 wB = *(const ulonglong2*)&Wi[k2 * D + col4 + 2];
#pragma unroll
            for (int i = 0; i < 4; i++) {
                u64 hp = *(const u64*)&FS[(nb4 + i) * DFF + k2 * 2];
                acc2[i][0] = ffma2(hp, wA.x, acc2[i][0]);
                acc2[i][1] = ffma2(hp, wA.y, acc2[i][1]);
                acc2[i][2] = ffma2(hp, wB.x, acc2[i][2]);
                acc2[i][3] = ffma2(hp, wB.y, acc2[i][3]);
            }
        }
        __syncthreads();
        float4 b2v = *(const float4*)&b2[col4];
#pragma unroll
        for (int i = 0; i < 4; i++) {
            float4 x = *(float4*)&XS[(nb4 + i) * D + col4];
            x.x += hsum2(acc2[i][0]) + b2v.x;
            x.y += hsum2(acc2[i][1]) + b2v.y;
            x.z += hsum2(acc2[i][2]) + b2v.z;
            x.w += hsum2(acc2[i][3]) + b2v.w;
            *(float4*)&XS[(nb4 + i) * D + col4] = x;
        }
    }
    __syncthreads();

    // step 6: LN2 -> global out
    warp_ln4(XS, ln2g, ln2b, out + (long)n0 * D, t);
}

// ---------------- launch ----------------------------------------------------
extern "C" void kernel_launch(void* const* d_in, const int* in_sizes, int n_in,
                              void* d_out, int out_size)
{
    const float* h    = (const float*)d_in[0];
    const int*   src  = (const int*)  d_in[1];
    const int*   dst  = (const int*)  d_in[2];
    const float* Wq   = (const float*)d_in[3];
    const float* Wk   = (const float*)d_in[4];
    const float* Wv   = (const float*)d_in[5];
    const float* Wo   = (const float*)d_in[6];
    const float* bo   = (const float*)d_in[7];
    const float* ln1g = (const float*)d_in[8];
    const float* ln1b = (const float*)d_in[9];
    const float* W1   = (const float*)d_in[10];
    const float* b1   = (const float*)d_in[11];
    const float* W2   = (const float*)d_in[12];
    const float* b2   = (const float*)d_in[13];
    const float* ln2g = (const float*)d_in[14];
    const float* ln2b = (const float*)d_in[15];
    float* out = (float*)d_out;

    dim3 igrid(64, 6);
    interleave_kernel<<<igrid, 256>>>(Wq, Wk, Wv, Wo, W1, W2);
    zero_cnt_kernel<<<(N_NODES + 255) / 256, 256>>>();
    scatter_kernel<<<N_EDGES / 256, 256>>>(src, dst);
    dim3 qgrid((N_NODES + 63) / 64, 3);
    qkv_kernel<<<qgrid, 256>>>(h);
    agg_kernel<<<N_NODES / 8, 256>>>();
    epi_kernel<<<N_NODES / 32, 256>>>(h, bo, ln1g, ln1b,
                                      b1, b2, ln2g, ln2b, out);
}

// round 6
// speedup vs baseline: 1.7298x; 1.7298x over previous
#include <cuda_runtime.h>

#define N_NODES 100000
#define N_EDGES 1600000
#define D 128
#define H 8
#define DH 16
#define DFF 256
#define CAP 96          // max in-degree capacity (Poisson mean 16; P(>96) ~ 0)

// ---------------- scratch (device globals; no allocation allowed) ----------
__device__ float g_Q[N_NODES * D];
__device__ float g_KV[(long)N_NODES * 2 * D];   // [node][K 0..127 | V 128..255]
__device__ float g_wV[N_NODES * D];
__device__ float g_z[N_NODES * H];
__device__ int   g_cnt[N_NODES];
__device__ int   g_csr[(long)N_NODES * CAP];

// k-pair interleaved weights for qkv only
__device__ float2 g_Wqi[64 * D];
__device__ float2 g_Wki[64 * D];
__device__ float2 g_Wvi[64 * D];

// ---------------- packed f32x2 helpers -------------------------------------
typedef unsigned long long u64;

__device__ __forceinline__ u64 ffma2(u64 a, u64 b, u64 c) {
    u64 d;
    asm("fma.rn.f32x2 %0, %1, %2, %3;" : "=l"(d) : "l"(a), "l"(b), "l"(c));
    return d;
}
__device__ __forceinline__ u64 dup2(float s) {
    u64 d;
    asm("mov.b64 %0, {%1, %1};" : "=l"(d) : "f"(s));
    return d;
}
union U2 { u64 p; float2 f; };
__device__ __forceinline__ float hsum2(u64 a) { U2 u; u.p = a; return u.f.x + u.f.y; }
union V4 { u64 p[2]; float4 f; };

// ---------------- interleave qkv weights ------------------------------------
__global__ void interleave_kernel(
    const float* __restrict__ Wq, const float* __restrict__ Wk,
    const float* __restrict__ Wv)
{
    int m = blockIdx.y;
    const float* W = (m == 0) ? Wq : (m == 1) ? Wk : Wv;
    float2* O = (m == 0) ? g_Wqi : (m == 1) ? g_Wki : g_Wvi;
    int idx = blockIdx.x * 256 + threadIdx.x;
    if (idx >= 64 * D) return;
    int k2 = idx / D, c = idx % D;
    O[idx] = make_float2(W[(2 * k2) * D + c], W[(2 * k2 + 1) * D + c]);
}

// ---------------- zero in-degree counters ----------------------------------
__global__ void zero_cnt_kernel() {
    int i = blockIdx.x * blockDim.x + threadIdx.x;
    if (i < N_NODES) g_cnt[i] = 0;
}

// ---------------- bucket edges by dst --------------------------------------
__global__ __launch_bounds__(256) void scatter_kernel(
    const int* __restrict__ src, const int* __restrict__ dst)
{
    int e = blockIdx.x * 256 + threadIdx.x;
    if (e >= N_EDGES) return;
    int d = dst[e];
    int pos = atomicAdd(&g_cnt[d], 1);
    if (pos < CAP) g_csr[(long)d * CAP + pos] = src[e];
}

// ---------------- QKV projection: k-packed FFMA2 (R4 measured 293us) -------
// grid = (3125, 3). 256 threads, 32-node tile. Thread: 8 nodes x 2 cols.
__global__ __launch_bounds__(256, 4) void qkv_kernel(const float* __restrict__ h)
{
    __shared__ float hs[32 * D];
    int t = threadIdx.x;
    int n0 = blockIdx.x * 32;
    int wsel = blockIdx.y;

    {
        int w = t >> 5, lane = t & 31;
#pragma unroll
        for (int j = 0; j < 4; j++) {
            int n = w + j * 8;
            float4 v = ((const float4*)h)[(long)(n0 + n) * (D / 4) + lane];
            *(float4*)&hs[n * D + lane * 4] = v;
        }
    }
    __syncthreads();

    const u64* __restrict__ Wi = (const u64*)((wsel == 0) ? g_Wqi
                                : (wsel == 1) ? g_Wki : g_Wvi);

    int col2 = (t & 63) * 2;
    int nb   = (t >> 6) * 8;

    u64 acc2[8][2];
#pragma unroll
    for (int i = 0; i < 8; i++) { acc2[i][0] = 0ull; acc2[i][1] = 0ull; }

#pragma unroll 4
    for (int k2 = 0; k2 < 64; k2++) {
        ulonglong2 wp = *(const ulonglong2*)&Wi[k2 * D + col2];
#pragma unroll
        for (int i = 0; i < 8; i++) {
            u64 hp = *(const u64*)&hs[(nb + i) * D + k2 * 2];
            acc2[i][0] = ffma2(hp, wp.x, acc2[i][0]);
            acc2[i][1] = ffma2(hp, wp.y, acc2[i][1]);
        }
    }

    float* O = (wsel == 0) ? g_Q : (wsel == 1) ? g_KV : g_KV + D;
    long rowstride = (wsel == 0) ? D : 2 * D;
#pragma unroll
    for (int i = 0; i < 8; i++) {
        int n = n0 + nb + i;
        float2 r = make_float2(hsum2(acc2[i][0]), hsum2(acc2[i][1]));
        *(float2*)&O[(long)n * rowstride + col2] = r;
    }
}

// ---------------- aggregation: TWO warps per dst node ----------------------
// 256 threads = 8 warps = 4 nodes/block. Warp parity p takes edges p, p+2, ...
// Partials combined through smem: halves the per-node critical path and the
// Poisson-degree imbalance across the block.
__global__ __launch_bounds__(256) void agg_kernel()
{
    __shared__ float4 part[8][32];
    __shared__ float  partz[8][8];

    int w = threadIdx.x >> 5, lane = threadIdx.x & 31;
    int nl = w >> 1;
    int parity = w & 1;
    int n = blockIdx.x * 4 + nl;          // 25000 blocks exact

    float4 q = *(const float4*)&g_Q[(long)n * D + lane * 4];
    float4 acc = make_float4(0.f, 0.f, 0.f, 0.f);
    float accz = 0.f;

    int deg = g_cnt[n];
    if (deg > CAP) deg = CAP;
    const int* __restrict__ lst = &g_csr[(long)n * CAP];

    int j = parity;
    if (j < deg) {
        int s = lst[j];
        const float* kvp = &g_KV[(long)s * 2 * D];
        float4 k = *(const float4*)&kvp[lane * 4];
        float4 v = *(const float4*)&kvp[D + lane * 4];
        for (; j < deg; j += 2) {
            float4 kc = k, vc = v;
            if (j + 2 < deg) {
                int s2 = lst[j + 2];
                const float* kvp2 = &g_KV[(long)s2 * 2 * D];
                k = *(const float4*)&kvp2[lane * 4];
                v = *(const float4*)&kvp2[D + lane * 4];
            }
            float ps = kc.x * q.x + kc.y * q.y + kc.z * q.z + kc.w * q.w;
            ps += __shfl_xor_sync(0xffffffff, ps, 1);
            ps += __shfl_xor_sync(0xffffffff, ps, 2);
            float sc = __expf(fminf(fmaxf(ps * 0.25f, -5.f), 5.f));
            acc.x += sc * vc.x; acc.y += sc * vc.y;
            acc.z += sc * vc.z; acc.w += sc * vc.w;
            accz += sc;
        }
    }

    part[w][lane] = acc;
    if ((lane & 3) == 0) partz[w][lane >> 2] = accz;
    __syncthreads();

    if (parity == 0) {
        float4 a = part[w][lane], b = part[w + 1][lane];
        a.x += b.x; a.y += b.y; a.z += b.z; a.w += b.w;
        *(float4*)&g_wV[(long)n * D + lane * 4] = a;
        if ((lane & 3) == 0) {
            int head = lane >> 2;
            g_z[(long)n * H + head] = partz[w][head] + partz[w + 1][head];
        }
    }
}

// ---------------- epilogue (round-3 bench dup-mov version, ~300us) ---------
__device__ __forceinline__ void warp_ln4(float* buf, const float* __restrict__ g,
                                         const float* __restrict__ b,
                                         float* outbase, int t)
{
    int w = t >> 5, lane = t & 31;
    float4 gv = *(const float4*)&g[lane * 4];
    float4 bv = *(const float4*)&b[lane * 4];
#pragma unroll
    for (int i = 0; i < 4; i++) {
        int n = w * 4 + i;
        float4 v = *(float4*)&buf[n * D + lane * 4];
        float s  = v.x + v.y + v.z + v.w;
        float sq = v.x * v.x + v.y * v.y + v.z * v.z + v.w * v.w;
#pragma unroll
        for (int off = 16; off >= 1; off >>= 1) {
            s  += __shfl_xor_sync(0xffffffff, s, off);
            sq += __shfl_xor_sync(0xffffffff, sq, off);
        }
        float mu  = s * (1.f / D);
        float var = sq * (1.f / D) - mu * mu;
        float rs  = rsqrtf(var + 1e-5f);
        float4 o;
        o.x = (v.x - mu) * rs * gv.x + bv.x;
        o.y = (v.y - mu) * rs * gv.y + bv.y;
        o.z = (v.z - mu) * rs * gv.z + bv.z;
        o.w = (v.w - mu) * rs * gv.w + bv.w;
        *(float4*)&outbase[n * D + lane * 4] = o;
    }
}

__global__ __launch_bounds__(256) void epi_kernel(
    const float* __restrict__ h,
    const float* __restrict__ Wo, const float* __restrict__ bo,
    const float* __restrict__ ln1g, const float* __restrict__ ln1b,
    const float* __restrict__ W1, const float* __restrict__ b1,
    const float* __restrict__ W2, const float* __restrict__ b2,
    const float* __restrict__ ln2g, const float* __restrict__ ln2b,
    float* __restrict__ out)
{
    __shared__ float sm[12288];           // 48KB
    float* XS = sm;                       // [32][128]
    float* A  = sm + 4096;                // [32][128]; later reused as FS
    float* FS = sm + 4096;                // [32][256]

    int t = threadIdx.x;
    int n0 = blockIdx.x * 32;

    // step 1: h_attn = wV / (z + eps)
    {
        int nl = t >> 3;
        int head = t & 7;
        int gn = n0 + nl;
        float inv = 1.f / (g_z[(long)gn * H + head] + 1e-6f);
        const float4* s4 = (const float4*)&g_wV[(long)gn * D + head * 16];
        float4* a4 = (float4*)&A[nl * D + head * 16];
#pragma unroll
        for (int j = 0; j < 4; j++) {
            float4 v = s4[j];
            v.x *= inv; v.y *= inv; v.z *= inv; v.w *= inv;
            a4[j] = v;
        }
    }
    __syncthreads();

    int col = (t & 31) * 4;
    int nb4 = (t >> 5) * 4;

    // step 2: XS = h + A @ Wo + bo
    {
        u64 acc[4][2];
#pragma unroll
        for (int i = 0; i < 4; i++) { acc[i][0] = 0ull; acc[i][1] = 0ull; }
#pragma unroll 4
        for (int k = 0; k < D; k += 2) {
            ulonglong2 w0 = *(const ulonglong2*)&Wo[k * D + col];
            ulonglong2 w1 = *(const ulonglong2*)&Wo[(k + 1) * D + col];
#pragma unroll
            for (int i = 0; i < 4; i++) {
                float2 ak = *(const float2*)&A[(nb4 + i) * D + k];
                u64 d0 = dup2(ak.x), d1 = dup2(ak.y);
                acc[i][0] = ffma2(d0, w0.x, acc[i][0]);
                acc[i][1] = ffma2(d0, w0.y, acc[i][1]);
                acc[i][0] = ffma2(d1, w1.x, acc[i][0]);
                acc[i][1] = ffma2(d1, w1.y, acc[i][1]);
            }
        }
        float4 bov = *(const float4*)&bo[col];
        __syncthreads();
#pragma unroll
        for (int i = 0; i < 4; i++) {
            float4 hv = *(const float4*)&h[(long)(n0 + nb4 + i) * D + col];
            V4 v; v.p[0] = acc[i][0]; v.p[1] = acc[i][1];
            float4 x;
            x.x = hv.x + v.f.x + bov.x;
            x.y = hv.y + v.f.y + bov.y;
            x.z = hv.z + v.f.z + bov.z;
            x.w = hv.w + v.f.w + bov.w;
            *(float4*)&XS[(nb4 + i) * D + col] = x;
        }
    }
    __syncthreads();

    // step 3: LN1 in place on XS
    warp_ln4(XS, ln1g, ln1b, XS, t);
    __syncthreads();

    // step 4: FS = relu(XS @ W1 + b1)
    {
        int c1  = (t & 63) * 4;
        int nb8 = (t >> 6) * 8;
        u64 acc[8][2];
#pragma unroll
        for (int i = 0; i < 8; i++) { acc[i][0] = 0ull; acc[i][1] = 0ull; }
#pragma unroll 2
        for (int k = 0; k < D; k += 2) {
            ulonglong2 w0 = *(const ulonglong2*)&W1[k * DFF + c1];
            ulonglong2 w1 = *(const ulonglong2*)&W1[(k + 1) * DFF + c1];
#pragma unroll
            for (int i = 0; i < 8; i++) {
                float2 xk = *(const float2*)&XS[(nb8 + i) * D + k];
                u64 d0 = dup2(xk.x), d1 = dup2(xk.y);
                acc[i][0] = ffma2(d0, w0.x, acc[i][0]);
                acc[i][1] = ffma2(d0, w0.y, acc[i][1]);
                acc[i][0] = ffma2(d1, w1.x, acc[i][0]);
                acc[i][1] = ffma2(d1, w1.y, acc[i][1]);
            }
        }
        float4 b1v = *(const float4*)&b1[c1];
        __syncthreads();
#pragma unroll
        for (int i = 0; i < 8; i++) {
            V4 v; v.p[0] = acc[i][0]; v.p[1] = acc[i][1];
            float4 f;
            f.x = fmaxf(v.f.x + b1v.x, 0.f);
            f.y = fmaxf(v.f.y + b1v.y, 0.f);
            f.z = fmaxf(v.f.z + b1v.z, 0.f);
            f.w = fmaxf(v.f.w + b1v.w, 0.f);
            *(float4*)&FS[(nb8 + i) * DFF + c1] = f;
        }
    }
    __syncthreads();

    // step 5: pre-LN2 = XS + FS @ W2 + b2
    {
        u64 acc[4][2];
#pragma unroll
        for (int i = 0; i < 4; i++) { acc[i][0] = 0ull; acc[i][1] = 0ull; }
#pragma unroll 2
        for (int k = 0; k < DFF; k += 2) {
            ulonglong2 w0 = *(const ulonglong2*)&W2[k * D + col];
            ulonglong2 w1 = *(const ulonglong2*)&W2[(k + 1) * D + col];
#pragma unroll
            for (int i = 0; i < 4; i++) {
                float2 fk = *(const float2*)&FS[(nb4 + i) * DFF + k];
                u64 d0 = dup2(fk.x), d1 = dup2(fk.y);
                acc[i][0] = ffma2(d0, w0.x, acc[i][0]);
                acc[i][1] = ffma2(d0, w0.y, acc[i][1]);
                acc[i][0] = ffma2(d1, w1.x, acc[i][0]);
                acc[i][1] = ffma2(d1, w1.y, acc[i][1]);
            }
        }
        __syncthreads();
        float4 b2v = *(const float4*)&b2[col];
#pragma unroll
        for (int i = 0; i < 4; i++) {
            float4 x = *(float4*)&XS[(nb4 + i) * D + col];
            V4 v; v.p[0] = acc[i][0]; v.p[1] = acc[i][1];
            x.x += v.f.x + b2v.x;
            x.y += v.f.y + b2v.y;
            x.z += v.f.z + b2v.z;
            x.w += v.f.w + b2v.w;
            *(float4*)&XS[(nb4 + i) * D + col] = x;
        }
    }
    __syncthreads();

    // step 6: LN2 -> global out
    warp_ln4(XS, ln2g, ln2b, out + (long)n0 * D, t);
}

// ---------------- launch ----------------------------------------------------
extern "C" void kernel_launch(void* const* d_in, const int* in_sizes, int n_in,
                              void* d_out, int out_size)
{
    const float* h    = (const float*)d_in[0];
    const int*   src  = (const int*)  d_in[1];
    const int*   dst  = (const int*)  d_in[2];
    const float* Wq   = (const float*)d_in[3];
    const float* Wk   = (const float*)d_in[4];
    const float* Wv   = (const float*)d_in[5];
    const float* Wo   = (const float*)d_in[6];
    const float* bo   = (const float*)d_in[7];
    const float* ln1g = (const float*)d_in[8];
    const float* ln1b = (const float*)d_in[9];
    const float* W1   = (const float*)d_in[10];
    const float* b1   = (const float*)d_in[11];
    const float* W2   = (const float*)d_in[12];
    const float* b2   = (const float*)d_in[13];
    const float* ln2g = (const float*)d_in[14];
    const float* ln2b = (const float*)d_in[15];
    float* out = (float*)d_out;

    dim3 igrid(32, 3);
    interleave_kernel<<<igrid, 256>>>(Wq, Wk, Wv);
    zero_cnt_kernel<<<(N_NODES + 255) / 256, 256>>>();
    scatter_kernel<<<N_EDGES / 256, 256>>>(src, dst);
    dim3 qgrid(N_NODES / 32, 3);
    qkv_kernel<<<qgrid, 256>>>(h);
    agg_kernel<<<N_NODES / 4, 256>>>();
    epi_kernel<<<N_NODES / 32, 256>>>(h, Wo, bo, ln1g, ln1b,
                                      W1, b1, W2, b2, ln2g, ln2b, out);
}

// round 7
// speedup vs baseline: 1.8072x; 1.0448x over previous
#include <cuda_runtime.h>

#define N_NODES 100000
#define N_EDGES 1600000
#define D 128
#define H 8
#define DH 16
#define DFF 256
#define CAP 96          // max in-degree capacity (Poisson mean 16; P(>96) ~ 0)

// ---------------- scratch (device globals; no allocation allowed) ----------
__device__ float g_Q[N_NODES * D];
__device__ float g_KV[(long)N_NODES * 2 * D];   // [node][K 0..127 | V 128..255]
__device__ float g_wV[N_NODES * D];
__device__ float g_z[N_NODES * H];
__device__ int   g_cnt[N_NODES];
__device__ int   g_csr[(long)N_NODES * CAP];

// k-pair interleaved weights for qkv only
__device__ float2 g_Wqi[64 * D];
__device__ float2 g_Wki[64 * D];
__device__ float2 g_Wvi[64 * D];

// ---------------- packed f32x2 helpers -------------------------------------
typedef unsigned long long u64;

__device__ __forceinline__ u64 ffma2(u64 a, u64 b, u64 c) {
    u64 d;
    asm("fma.rn.f32x2 %0, %1, %2, %3;" : "=l"(d) : "l"(a), "l"(b), "l"(c));
    return d;
}
__device__ __forceinline__ u64 dup2(float s) {
    u64 d;
    asm("mov.b64 %0, {%1, %1};" : "=l"(d) : "f"(s));
    return d;
}
union U2 { u64 p; float2 f; };
__device__ __forceinline__ float hsum2(u64 a) { U2 u; u.p = a; return u.f.x + u.f.y; }
union V4 { u64 p[2]; float4 f; };

// ---------------- interleave qkv weights ------------------------------------
__global__ void interleave_kernel(
    const float* __restrict__ Wq, const float* __restrict__ Wk,
    const float* __restrict__ Wv)
{
    int m = blockIdx.y;
    const float* W = (m == 0) ? Wq : (m == 1) ? Wk : Wv;
    float2* O = (m == 0) ? g_Wqi : (m == 1) ? g_Wki : g_Wvi;
    int idx = blockIdx.x * 256 + threadIdx.x;
    if (idx >= 64 * D) return;
    int k2 = idx / D, c = idx % D;
    O[idx] = make_float2(W[(2 * k2) * D + c], W[(2 * k2 + 1) * D + c]);
}

// ---------------- zero in-degree counters ----------------------------------
__global__ void zero_cnt_kernel() {
    int i = blockIdx.x * blockDim.x + threadIdx.x;
    if (i < N_NODES) g_cnt[i] = 0;
}

// ---------------- bucket edges by dst --------------------------------------
__global__ __launch_bounds__(256) void scatter_kernel(
    const int* __restrict__ src, const int* __restrict__ dst)
{
    int e = blockIdx.x * 256 + threadIdx.x;
    if (e >= N_EDGES) return;
    int d = dst[e];
    int pos = atomicAdd(&g_cnt[d], 1);
    if (pos < CAP) g_csr[(long)d * CAP + pos] = src[e];
}

// ---------------- QKV projection: k-packed FFMA2, LDS.128 h loads ----------
// grid = (3125, 3). 256 threads, 32-node tile. Thread: 8 nodes x 2 cols.
// Per k4 (4 k-values): 8 LDS.128 + 2 LDG.128 + 32 FFMA2 per thread.
__global__ __launch_bounds__(256, 4) void qkv_kernel(const float* __restrict__ h)
{
    __shared__ float hs[32 * D];
    int t = threadIdx.x;
    int n0 = blockIdx.x * 32;
    int wsel = blockIdx.y;

    {
        int w = t >> 5, lane = t & 31;
#pragma unroll
        for (int j = 0; j < 4; j++) {
            int n = w + j * 8;
            float4 v = ((const float4*)h)[(long)(n0 + n) * (D / 4) + lane];
            *(float4*)&hs[n * D + lane * 4] = v;
        }
    }
    __syncthreads();

    const u64* __restrict__ Wi = (const u64*)((wsel == 0) ? g_Wqi
                                : (wsel == 1) ? g_Wki : g_Wvi);

    int col2 = (t & 63) * 2;
    int nb   = (t >> 6) * 8;

    u64 acc2[8][2];
#pragma unroll
    for (int i = 0; i < 8; i++) { acc2[i][0] = 0ull; acc2[i][1] = 0ull; }

#pragma unroll 4
    for (int k4 = 0; k4 < 32; k4++) {
        // weight k-pairs for k2 = 2*k4 and 2*k4+1
        ulonglong2 wp0 = *(const ulonglong2*)&Wi[(2 * k4) * D + col2];
        ulonglong2 wp1 = *(const ulonglong2*)&Wi[(2 * k4 + 1) * D + col2];
#pragma unroll
        for (int i = 0; i < 8; i++) {
            ulonglong2 hv = *(const ulonglong2*)&hs[(nb + i) * D + k4 * 4];
            acc2[i][0] = ffma2(hv.x, wp0.x, acc2[i][0]);
            acc2[i][1] = ffma2(hv.x, wp0.y, acc2[i][1]);
            acc2[i][0] = ffma2(hv.y, wp1.x, acc2[i][0]);
            acc2[i][1] = ffma2(hv.y, wp1.y, acc2[i][1]);
        }
    }

    float* O = (wsel == 0) ? g_Q : (wsel == 1) ? g_KV : g_KV + D;
    long rowstride = (wsel == 0) ? D : 2 * D;
#pragma unroll
    for (int i = 0; i < 8; i++) {
        int n = n0 + nb + i;
        float2 r = make_float2(hsum2(acc2[i][0]), hsum2(acc2[i][1]));
        *(float2*)&O[(long)n * rowstride + col2] = r;
    }
}

// ---------------- aggregation: one warp per dst node (R3, measured 168us) --
__global__ __launch_bounds__(256) void agg_kernel()
{
    int n = blockIdx.x * 8 + (threadIdx.x >> 5);
    int lane = threadIdx.x & 31;

    float4 q = *(const float4*)&g_Q[(long)n * D + lane * 4];
    float4 acc = make_float4(0.f, 0.f, 0.f, 0.f);
    float accz = 0.f;

    int deg = g_cnt[n];
    if (deg > CAP) deg = CAP;
    const int* __restrict__ lst = &g_csr[(long)n * CAP];

    if (deg > 0) {
        int s = lst[0];
        const float* kvp = &g_KV[(long)s * 2 * D];
        float4 k = *(const float4*)&kvp[lane * 4];
        float4 v = *(const float4*)&kvp[D + lane * 4];
        for (int j = 0; j < deg; j++) {
            float4 kc = k, vc = v;
            if (j + 1 < deg) {
                int s2 = lst[j + 1];
                const float* kvp2 = &g_KV[(long)s2 * 2 * D];
                k = *(const float4*)&kvp2[lane * 4];
                v = *(const float4*)&kvp2[D + lane * 4];
            }
            float ps = kc.x * q.x + kc.y * q.y + kc.z * q.z + kc.w * q.w;
            ps += __shfl_xor_sync(0xffffffff, ps, 1);
            ps += __shfl_xor_sync(0xffffffff, ps, 2);
            float sc = __expf(fminf(fmaxf(ps * 0.25f, -5.f), 5.f));
            acc.x += sc * vc.x; acc.y += sc * vc.y;
            acc.z += sc * vc.z; acc.w += sc * vc.w;
            accz += sc;
        }
    }

    *(float4*)&g_wV[(long)n * D + lane * 4] = acc;
    if ((lane & 3) == 0) g_z[(long)n * H + (lane >> 2)] = accz;
}

// ---------------- epilogue (dup-mov version, reproduced ~314us) ------------
__device__ __forceinline__ void warp_ln4(float* buf, const float* __restrict__ g,
                                         const float* __restrict__ b,
                                         float* outbase, int t)
{
    int w = t >> 5, lane = t & 31;
    float4 gv = *(const float4*)&g[lane * 4];
    float4 bv = *(const float4*)&b[lane * 4];
#pragma unroll
    for (int i = 0; i < 4; i++) {
        int n = w * 4 + i;
        float4 v = *(float4*)&buf[n * D + lane * 4];
        float s  = v.x + v.y + v.z + v.w;
        float sq = v.x * v.x + v.y * v.y + v.z * v.z + v.w * v.w;
#pragma unroll
        for (int off = 16; off >= 1; off >>= 1) {
            s  += __shfl_xor_sync(0xffffffff, s, off);
            sq += __shfl_xor_sync(0xffffffff, sq, off);
        }
        float mu  = s * (1.f / D);
        float var = sq * (1.f / D) - mu * mu;
        float rs  = rsqrtf(var + 1e-5f);
        float4 o;
        o.x = (v.x - mu) * rs * gv.x + bv.x;
        o.y = (v.y - mu) * rs * gv.y + bv.y;
        o.z = (v.z - mu) * rs * gv.z + bv.z;
        o.w = (v.w - mu) * rs * gv.w + bv.w;
        *(float4*)&outbase[n * D + lane * 4] = o;
    }
}

__global__ __launch_bounds__(256) void epi_kernel(
    const float* __restrict__ h,
    const float* __restrict__ Wo, const float* __restrict__ bo,
    const float* __restrict__ ln1g, const float* __restrict__ ln1b,
    const float* __restrict__ W1, const float* __restrict__ b1,
    const float* __restrict__ W2, const float* __restrict__ b2,
    const float* __restrict__ ln2g, const float* __restrict__ ln2b,
    float* __restrict__ out)
{
    __shared__ float sm[12288];           // 48KB
    float* XS = sm;                       // [32][128]
    float* A  = sm + 4096;                // [32][128]; later reused as FS
    float* FS = sm + 4096;                // [32][256]

    int t = threadIdx.x;
    int n0 = blockIdx.x * 32;

    // step 1: h_attn = wV / (z + eps)
    {
        int nl = t >> 3;
        int head = t & 7;
        int gn = n0 + nl;
        float inv = 1.f / (g_z[(long)gn * H + head] + 1e-6f);
        const float4* s4 = (const float4*)&g_wV[(long)gn * D + head * 16];
        float4* a4 = (float4*)&A[nl * D + head * 16];
#pragma unroll
        for (int j = 0; j < 4; j++) {
            float4 v = s4[j];
            v.x *= inv; v.y *= inv; v.z *= inv; v.w *= inv;
            a4[j] = v;
        }
    }
    __syncthreads();

    int col = (t & 31) * 4;
    int nb4 = (t >> 5) * 4;

    // step 2: XS = h + A @ Wo + bo
    {
        u64 acc[4][2];
#pragma unroll
        for (int i = 0; i < 4; i++) { acc[i][0] = 0ull; acc[i][1] = 0ull; }
#pragma unroll 4
        for (int k = 0; k < D; k += 2) {
            ulonglong2 w0 = *(const ulonglong2*)&Wo[k * D + col];
            ulonglong2 w1 = *(const ulonglong2*)&Wo[(k + 1) * D + col];
#pragma unroll
            for (int i = 0; i < 4; i++) {
                float2 ak = *(const float2*)&A[(nb4 + i) * D + k];
                u64 d0 = dup2(ak.x), d1 = dup2(ak.y);
                acc[i][0] = ffma2(d0, w0.x, acc[i][0]);
                acc[i][1] = ffma2(d0, w0.y, acc[i][1]);
                acc[i][0] = ffma2(d1, w1.x, acc[i][0]);
                acc[i][1] = ffma2(d1, w1.y, acc[i][1]);
            }
        }
        float4 bov = *(const float4*)&bo[col];
        __syncthreads();
#pragma unroll
        for (int i = 0; i < 4; i++) {
            float4 hv = *(const float4*)&h[(long)(n0 + nb4 + i) * D + col];
            V4 v; v.p[0] = acc[i][0]; v.p[1] = acc[i][1];
            float4 x;
            x.x = hv.x + v.f.x + bov.x;
            x.y = hv.y + v.f.y + bov.y;
            x.z = hv.z + v.f.z + bov.z;
            x.w = hv.w + v.f.w + bov.w;
            *(float4*)&XS[(nb4 + i) * D + col] = x;
        }
    }
    __syncthreads();

    // step 3: LN1 in place on XS
    warp_ln4(XS, ln1g, ln1b, XS, t);
    __syncthreads();

    // step 4: FS = relu(XS @ W1 + b1)
    {
        int c1  = (t & 63) * 4;
        int nb8 = (t >> 6) * 8;
        u64 acc[8][2];
#pragma unroll
        for (int i = 0; i < 8; i++) { acc[i][0] = 0ull; acc[i][1] = 0ull; }
#pragma unroll 2
        for (int k = 0; k < D; k += 2) {
            ulonglong2 w0 = *(const ulonglong2*)&W1[k * DFF + c1];
            ulonglong2 w1 = *(const ulonglong2*)&W1[(k + 1) * DFF + c1];
#pragma unroll
            for (int i = 0; i < 8; i++) {
                float2 xk = *(const float2*)&XS[(nb8 + i) * D + k];
                u64 d0 = dup2(xk.x), d1 = dup2(xk.y);
                acc[i][0] = ffma2(d0, w0.x, acc[i][0]);
                acc[i][1] = ffma2(d0, w0.y, acc[i][1]);
                acc[i][0] = ffma2(d1, w1.x, acc[i][0]);
                acc[i][1] = ffma2(d1, w1.y, acc[i][1]);
            }
        }
        float4 b1v = *(const float4*)&b1[c1];
        __syncthreads();
#pragma unroll
        for (int i = 0; i < 8; i++) {
            V4 v; v.p[0] = acc[i][0]; v.p[1] = acc[i][1];
            float4 f;
            f.x = fmaxf(v.f.x + b1v.x, 0.f);
            f.y = fmaxf(v.f.y + b1v.y, 0.f);
            f.z = fmaxf(v.f.z + b1v.z, 0.f);
            f.w = fmaxf(v.f.w + b1v.w, 0.f);
            *(float4*)&FS[(nb8 + i) * DFF + c1] = f;
        }
    }
    __syncthreads();

    // step 5: pre-LN2 = XS + FS @ W2 + b2
    {
        u64 acc[4][2];
#pragma unroll
        for (int i = 0; i < 4; i++) { acc[i][0] = 0ull; acc[i][1] = 0ull; }
#pragma unroll 2
        for (int k = 0; k < DFF; k += 2) {
            ulonglong2 w0 = *(const ulonglong2*)&W2[k * D + col];
            ulonglong2 w1 = *(const ulonglong2*)&W2[(k + 1) * D + col];
#pragma unroll
            for (int i = 0; i < 4; i++) {
                float2 fk = *(const float2*)&FS[(nb4 + i) * DFF + k];
                u64 d0 = dup2(fk.x), d1 = dup2(fk.y);
                acc[i][0] = ffma2(d0, w0.x, acc[i][0]);
                acc[i][1] = ffma2(d0, w0.y, acc[i][1]);
                acc[i][0] = ffma2(d1, w1.x, acc[i][0]);
                acc[i][1] = ffma2(d1, w1.y, acc[i][1]);
            }
        }
        __syncthreads();
        float4 b2v = *(const float4*)&b2[col];
#pragma unroll
        for (int i = 0; i < 4; i++) {
            float4 x = *(float4*)&XS[(nb4 + i) * D + col];
            V4 v; v.p[0] = acc[i][0]; v.p[1] = acc[i][1];
            x.x += v.f.x + b2v.x;
            x.y += v.f.y + b2v.y;
            x.z += v.f.z + b2v.z;
            x.w += v.f.w + b2v.w;
            *(float4*)&XS[(nb4 + i) * D + col] = x;
        }
    }
    __syncthreads();

    // step 6: LN2 -> global out
    warp_ln4(XS, ln2g, ln2b, out + (long)n0 * D, t);
}

// ---------------- launch ----------------------------------------------------
extern "C" void kernel_launch(void* const* d_in, const int* in_sizes, int n_in,
                              void* d_out, int out_size)
{
    const float* h    = (const float*)d_in[0];
    const int*   src  = (const int*)  d_in[1];
    const int*   dst  = (const int*)  d_in[2];
    const float* Wq   = (const float*)d_in[3];
    const float* Wk   = (const float*)d_in[4];
    const float* Wv   = (const float*)d_in[5];
    const float* Wo   = (const float*)d_in[6];
    const float* bo   = (const float*)d_in[7];
    const float* ln1g = (const float*)d_in[8];
    const float* ln1b = (const float*)d_in[9];
    const float* W1   = (const float*)d_in[10];
    const float* b1   = (const float*)d_in[11];
    const float* W2   = (const float*)d_in[12];
    const float* b2   = (const float*)d_in[13];
    const float* ln2g = (const float*)d_in[14];
    const float* ln2b = (const float*)d_in[15];
    float* out = (float*)d_out;

    dim3 igrid(32, 3);
    interleave_kernel<<<igrid, 256>>>(Wq, Wk, Wv);
    zero_cnt_kernel<<<(N_NODES + 255) / 256, 256>>>();
    scatter_kernel<<<N_EDGES / 256, 256>>>(src, dst);
    dim3 qgrid(N_NODES / 32, 3);
    qkv_kernel<<<qgrid, 256>>>(h);
    agg_kernel<<<N_NODES / 8, 256>>>();
    epi_kernel<<<N_NODES / 32, 256>>>(h, Wo, bo, ln1g, ln1b,
                                      W1, b1, W2, b2, ln2g, ln2b, out);
}

// round 9
// speedup vs baseline: 2.1746x; 1.2033x over previous
#include <cuda_runtime.h>
#include <cuda_bf16.h>
#include <cstdint>

#define N_NODES 100000
#define N_EDGES 1600000
#define D 128
#define H 8
#define DH 16
#define DFF 256
#define CAP 96

// ---------------- scratch (device globals; no allocation allowed) ----------
__device__ float g_Q[N_NODES * D];
__device__ float g_KV[(long)N_NODES * 2 * D];   // [node][K 0..127 | V 128..255]
__device__ float g_wV[N_NODES * D];
__device__ float g_z[N_NODES * H];
__device__ int   g_cnt[N_NODES];
__device__ int   g_csr[(long)N_NODES * CAP];

// bf16 hi/lo images of Wq,Wk,Wv: row-major [k][c] (exactly the MMA B operand)
__device__ __nv_bfloat16 g_Bh[3 * 128 * 128];
__device__ __nv_bfloat16 g_Bl[3 * 128 * 128];

// ---------------- packed f32x2 helpers (epi) --------------------------------
typedef unsigned long long u64;
__device__ __forceinline__ u64 ffma2(u64 a, u64 b, u64 c) {
    u64 d;
    asm("fma.rn.f32x2 %0, %1, %2, %3;" : "=l"(d) : "l"(a), "l"(b), "l"(c));
    return d;
}
__device__ __forceinline__ u64 dup2(float s) {
    u64 d;
    asm("mov.b64 %0, {%1, %1};" : "=l"(d) : "f"(s));
    return d;
}
union V4 { u64 p[2]; float4 f; };

// ---------------- mma.sync helpers ------------------------------------------
__device__ __forceinline__ uint32_t smem_u32(const void* p) {
    uint32_t a;
    asm("{ .reg .u64 t; cvta.to.shared.u64 t, %1; cvt.u32.u64 %0, t; }"
        : "=r"(a) : "l"(p));
    return a;
}
__device__ __forceinline__ void ldsm_x4(uint32_t* r, uint32_t addr) {
    asm volatile("ldmatrix.sync.aligned.m8n8.x4.shared.b16 {%0,%1,%2,%3}, [%4];"
                 : "=r"(r[0]), "=r"(r[1]), "=r"(r[2]), "=r"(r[3]) : "r"(addr));
}
__device__ __forceinline__ void ldsm_x4_t(uint32_t* r, uint32_t addr) {
    asm volatile("ldmatrix.sync.aligned.m8n8.x4.trans.shared.b16 {%0,%1,%2,%3}, [%4];"
                 : "=r"(r[0]), "=r"(r[1]), "=r"(r[2]), "=r"(r[3]) : "r"(addr));
}
__device__ __forceinline__ void mma_bf16(float* d, const uint32_t* a,
                                         uint32_t b0, uint32_t b1) {
    asm volatile(
        "mma.sync.aligned.m16n8k16.row.col.f32.bf16.bf16.f32 "
        "{%0,%1,%2,%3}, {%4,%5,%6,%7}, {%8,%9}, {%0,%1,%2,%3};"
        : "+f"(d[0]), "+f"(d[1]), "+f"(d[2]), "+f"(d[3])
        : "r"(a[0]), "r"(a[1]), "r"(a[2]), "r"(a[3]), "r"(b0), "r"(b1));
}

// ---------------- B prep: bf16 hi/lo of W ------------------------------------
__global__ void bprep_kernel(const float* __restrict__ Wq,
                             const float* __restrict__ Wk,
                             const float* __restrict__ Wv)
{
    int m = blockIdx.y;
    const float* W = (m == 0) ? Wq : (m == 1) ? Wk : Wv;
    int idx = blockIdx.x * 256 + threadIdx.x;       // 0..16383, grid.x = 64
    float x = W[idx];
    __nv_bfloat16 hb = __float2bfloat16(x);
    __nv_bfloat16 lb = __float2bfloat16(x - __bfloat162float(hb));
    g_Bh[m * 16384 + idx] = hb;
    g_Bl[m * 16384 + idx] = lb;
}

// ---------------- QKV via mma.sync bf16 hi/lo split --------------------------
// Block: 256 threads (8 warps), 128-node tile, all 3 matrices.
// smem: A_hi/A_lo/B_hi/B_lo, each [128][136] bf16 (272B padded rows).
#define ASTRIDE_B 272
#define PART_BYTES (128 * ASTRIDE_B)     // 34816
#define QKV_SMEM (4 * PART_BYTES)        // 139264

__global__ __launch_bounds__(256) void qkv_mma_kernel(const float* __restrict__ h)
{
    extern __shared__ char smem[];
    char* Ah = smem;
    char* Al = smem + PART_BYTES;
    char* Bh = smem + 2 * PART_BYTES;
    char* Bl = smem + 3 * PART_BYTES;

    int tid = threadIdx.x;
    int lane = tid & 31;
    int w = tid >> 5;
    int n0 = blockIdx.x * 128;

    // ---- convert h tile -> A_hi / A_lo (row r, col half) ----
    {
        int r = tid >> 1;
        int half = tid & 1;
        int n = n0 + r;
        const float4* hp = (const float4*)(h + (long)n * D + half * 64);
        char* dh = Ah + r * ASTRIDE_B + half * 128;
        char* dl = Al + r * ASTRIDE_B + half * 128;
        bool ok = (n < N_NODES);
#pragma unroll
        for (int j = 0; j < 16; j++) {
            float4 v = ok ? hp[j] : make_float4(0.f, 0.f, 0.f, 0.f);
            __nv_bfloat16 hx = __float2bfloat16(v.x), hy = __float2bfloat16(v.y);
            __nv_bfloat16 hz = __float2bfloat16(v.z), hw = __float2bfloat16(v.w);
            __nv_bfloat162 h0; h0.x = hx; h0.y = hy;
            __nv_bfloat162 h1; h1.x = hz; h1.y = hw;
            uint2 hu;
            hu.x = *reinterpret_cast<uint32_t*>(&h0);
            hu.y = *reinterpret_cast<uint32_t*>(&h1);
            *(uint2*)(dh + j * 8) = hu;
            __nv_bfloat162 l0, l1;
            l0.x = __float2bfloat16(v.x - __bfloat162float(hx));
            l0.y = __float2bfloat16(v.y - __bfloat162float(hy));
            l1.x = __float2bfloat16(v.z - __bfloat162float(hz));
            l1.y = __float2bfloat16(v.w - __bfloat162float(hw));
            uint2 lu;
            lu.x = *reinterpret_cast<uint32_t*>(&l0);
            lu.y = *reinterpret_cast<uint32_t*>(&l1);
            *(uint2*)(dl + j * 8) = lu;
        }
    }

    uint32_t AhU = smem_u32(Ah), AlU = smem_u32(Al);
    uint32_t BhU = smem_u32(Bh), BlU = smem_u32(Bl);

    // warp tiling: 2 x 4 -> m64 x n32 per warp
    int mbase = (w >> 2) * 64;
    int nbase = (w & 3) * 32;

#pragma unroll 1
    for (int m = 0; m < 3; m++) {
        __syncthreads();   // A conversion done / prev matrix mma reads done
        // copy B_m hi/lo into padded smem
        {
            const uint4* sh = (const uint4*)(g_Bh + m * 16384);
            const uint4* sl = (const uint4*)(g_Bl + m * 16384);
            for (int ch = tid; ch < 2048; ch += 256) {
                int row = ch >> 4, o = ch & 15;
                *(uint4*)(Bh + row * ASTRIDE_B + o * 16) = sh[ch];
                *(uint4*)(Bl + row * ASTRIDE_B + o * 16) = sl[ch];
            }
        }
        __syncthreads();

        float acc[4][4][4];
#pragma unroll
        for (int mt = 0; mt < 4; mt++)
#pragma unroll
            for (int nt = 0; nt < 4; nt++)
#pragma unroll
                for (int q = 0; q < 4; q++) acc[mt][nt][q] = 0.f;

#pragma unroll 1
        for (int pass = 0; pass < 3; pass++) {
            uint32_t Abase = (pass == 2) ? AlU : AhU;
            uint32_t Bbase = (pass == 1) ? BlU : BhU;
#pragma unroll 1
            for (int kt = 0; kt < 8; kt++) {
                uint32_t a[4][4];
#pragma unroll
                for (int mt = 0; mt < 4; mt++) {
                    uint32_t addr = Abase
                        + (mbase + mt * 16 + (lane & 15)) * ASTRIDE_B
                        + kt * 32 + (lane >> 4) * 16;
                    ldsm_x4(a[mt], addr);
                }
                int g = lane >> 3, r8 = lane & 7;
#pragma unroll
                for (int nt2 = 0; nt2 < 2; nt2++) {
                    uint32_t b[4];
                    uint32_t baddr = Bbase
                        + (kt * 16 + (g & 1) * 8 + r8) * ASTRIDE_B
                        + (nbase + nt2 * 16 + (g >> 1) * 8) * 2;
                    ldsm_x4_t(b, baddr);
#pragma unroll
                    for (int mt = 0; mt < 4; mt++) {
                        mma_bf16(acc[mt][nt2 * 2],     a[mt], b[0], b[1]);
                        mma_bf16(acc[mt][nt2 * 2 + 1], a[mt], b[2], b[3]);
                    }
                }
            }
        }

        // writeout
        float* base = (m == 0) ? g_Q : (m == 1) ? g_KV : g_KV + D;
        long stride = (m == 0) ? D : 2 * D;
        int gid = lane >> 2, q4 = lane & 3;
#pragma unroll
        for (int mt = 0; mt < 4; mt++)
#pragma unroll
            for (int nt = 0; nt < 4; nt++) {
                int row = n0 + mbase + mt * 16 + gid;
                int col = nbase + nt * 8 + q4 * 2;
                if (row < N_NODES)
                    *(float2*)&base[(long)row * stride + col] =
                        make_float2(acc[mt][nt][0], acc[mt][nt][1]);
                if (row + 8 < N_NODES)
                    *(float2*)&base[(long)(row + 8) * stride + col] =
                        make_float2(acc[mt][nt][2], acc[mt][nt][3]);
            }
    }
}

// ---------------- zero / scatter --------------------------------------------
__global__ void zero_cnt_kernel() {
    int i = blockIdx.x * blockDim.x + threadIdx.x;
    if (i < N_NODES) g_cnt[i] = 0;
}
__global__ __launch_bounds__(256) void scatter_kernel(
    const int* __restrict__ src, const int* __restrict__ dst)
{
    int e = blockIdx.x * 256 + threadIdx.x;
    if (e >= N_EDGES) return;
    int d = dst[e];
    int pos = atomicAdd(&g_cnt[d], 1);
    if (pos < CAP) g_csr[(long)d * CAP + pos] = src[e];
}

// ---------------- aggregation: one warp per dst node ------------------------
__global__ __launch_bounds__(256) void agg_kernel()
{
    int n = blockIdx.x * 8 + (threadIdx.x >> 5);
    int lane = threadIdx.x & 31;

    float4 q = *(const float4*)&g_Q[(long)n * D + lane * 4];
    float4 acc = make_float4(0.f, 0.f, 0.f, 0.f);
    float accz = 0.f;

    int deg = g_cnt[n];
    if (deg > CAP) deg = CAP;
    const int* __restrict__ lst = &g_csr[(long)n * CAP];

    if (deg > 0) {
        int s = lst[0];
        const float* kvp = &g_KV[(long)s * 2 * D];
        float4 k = *(const float4*)&kvp[lane * 4];
        float4 v = *(const float4*)&kvp[D + lane * 4];
        for (int j = 0; j < deg; j++) {
            float4 kc = k, vc = v;
            if (j + 1 < deg) {
                int s2 = lst[j + 1];
                const float* kvp2 = &g_KV[(long)s2 * 2 * D];
                k = *(const float4*)&kvp2[lane * 4];
                v = *(const float4*)&kvp2[D + lane * 4];
            }
            float ps = kc.x * q.x + kc.y * q.y + kc.z * q.z + kc.w * q.w;
            ps += __shfl_xor_sync(0xffffffff, ps, 1);
            ps += __shfl_xor_sync(0xffffffff, ps, 2);
            float sc = __expf(fminf(fmaxf(ps * 0.25f, -5.f), 5.f));
            acc.x += sc * vc.x; acc.y += sc * vc.y;
            acc.z += sc * vc.z; acc.w += sc * vc.w;
            accz += sc;
        }
    }

    *(float4*)&g_wV[(long)n * D + lane * 4] = acc;
    if ((lane & 3) == 0) g_z[(long)n * H + (lane >> 2)] = accz;
}

// ---------------- epilogue (dup-mov FFMA2 version) --------------------------
__device__ __forceinline__ void warp_ln4(float* buf, const float* __restrict__ g,
                                         const float* __restrict__ b,
                                         float* outbase, int t)
{
    int w = t >> 5, lane = t & 31;
    float4 gv = *(const float4*)&g[lane * 4];
    float4 bv = *(const float4*)&b[lane * 4];
#pragma unroll
    for (int i = 0; i < 4; i++) {
        int n = w * 4 + i;
        float4 v = *(float4*)&buf[n * D + lane * 4];
        float s  = v.x + v.y + v.z + v.w;
        float sq = v.x * v.x + v.y * v.y + v.z * v.z + v.w * v.w;
#pragma unroll
        for (int off = 16; off >= 1; off >>= 1) {
            s  += __shfl_xor_sync(0xffffffff, s, off);
            sq += __shfl_xor_sync(0xffffffff, sq, off);
        }
        float mu  = s * (1.f / D);
        float var = sq * (1.f / D) - mu * mu;
        float rs  = rsqrtf(var + 1e-5f);
        float4 o;
        o.x = (v.x - mu) * rs * gv.x + bv.x;
        o.y = (v.y - mu) * rs * gv.y + bv.y;
        o.z = (v.z - mu) * rs * gv.z + bv.z;
        o.w = (v.w - mu) * rs * gv.w + bv.w;
        *(float4*)&outbase[n * D + lane * 4] = o;
    }
}

__global__ __launch_bounds__(256) void epi_kernel(
    const float* __restrict__ h,
    const float* __restrict__ Wo, const float* __restrict__ bo,
    const float* __restrict__ ln1g, const float* __restrict__ ln1b,
    const float* __restrict__ W1, const float* __restrict__ b1,
    const float* __restrict__ W2, const float* __restrict__ b2,
    const float* __restrict__ ln2g, const float* __restrict__ ln2b,
    float* __restrict__ out)
{
    __shared__ float sm[12288];
    float* XS = sm;
    float* A  = sm + 4096;
    float* FS = sm + 4096;

    int t = threadIdx.x;
    int n0 = blockIdx.x * 32;

    {
        int nl = t >> 3;
        int head = t & 7;
        int gn = n0 + nl;
        float inv = 1.f / (g_z[(long)gn * H + head] + 1e-6f);
        const float4* s4 = (const float4*)&g_wV[(long)gn * D + head * 16];
        float4* a4 = (float4*)&A[nl * D + head * 16];
#pragma unroll
        for (int j = 0; j < 4; j++) {
            float4 v = s4[j];
            v.x *= inv; v.y *= inv; v.z *= inv; v.w *= inv;
            a4[j] = v;
        }
    }
    __syncthreads();

    int col = (t & 31) * 4;
    int nb4 = (t >> 5) * 4;

    {
        u64 acc[4][2];
#pragma unroll
        for (int i = 0; i < 4; i++) { acc[i][0] = 0ull; acc[i][1] = 0ull; }
#pragma unroll 4
        for (int k = 0; k < D; k += 2) {
            ulonglong2 w0 = *(const ulonglong2*)&Wo[k * D + col];
            ulonglong2 w1 = *(const ulonglong2*)&Wo[(k + 1) * D + col];
#pragma unroll
            for (int i = 0; i < 4; i++) {
                float2 ak = *(const float2*)&A[(nb4 + i) * D + k];
                u64 d0 = dup2(ak.x), d1 = dup2(ak.y);
                acc[i][0] = ffma2(d0, w0.x, acc[i][0]);
                acc[i][1] = ffma2(d0, w0.y, acc[i][1]);
                acc[i][0] = ffma2(d1, w1.x, acc[i][0]);
                acc[i][1] = ffma2(d1, w1.y, acc[i][1]);
            }
        }
        float4 bov = *(const float4*)&bo[col];
        __syncthreads();
#pragma unroll
        for (int i = 0; i < 4; i++) {
            float4 hv = *(const float4*)&h[(long)(n0 + nb4 + i) * D + col];
            V4 v; v.p[0] = acc[i][0]; v.p[1] = acc[i][1];
            float4 x;
            x.x = hv.x + v.f.x + bov.x;
            x.y = hv.y + v.f.y + bov.y;
            x.z = hv.z + v.f.z + bov.z;
            x.w = hv.w + v.f.w + bov.w;
            *(float4*)&XS[(nb4 + i) * D + col] = x;
        }
    }
    __syncthreads();

    warp_ln4(XS, ln1g, ln1b, XS, t);
    __syncthreads();

    {
        int c1  = (t & 63) * 4;
        int nb8 = (t >> 6) * 8;
        u64 acc[8][2];
#pragma unroll
        for (int i = 0; i < 8; i++) { acc[i][0] = 0ull; acc[i][1] = 0ull; }
#pragma unroll 2
        for (int k = 0; k < D; k += 2) {
            ulonglong2 w0 = *(const ulonglong2*)&W1[k * DFF + c1];
            ulonglong2 w1 = *(const ulonglong2*)&W1[(k + 1) * DFF + c1];
#pragma unroll
            for (int i = 0; i < 8; i++) {
                float2 xk = *(const float2*)&XS[(nb8 + i) * D + k];
                u64 d0 = dup2(xk.x), d1 = dup2(xk.y);
                acc[i][0] = ffma2(d0, w0.x, acc[i][0]);
                acc[i][1] = ffma2(d0, w0.y, acc[i][1]);
                acc[i][0] = ffma2(d1, w1.x, acc[i][0]);
                acc[i][1] = ffma2(d1, w1.y, acc[i][1]);
            }
        }
        float4 b1v = *(const float4*)&b1[c1];
        __syncthreads();
#pragma unroll
        for (int i = 0; i < 8; i++) {
            V4 v; v.p[0] = acc[i][0]; v.p[1] = acc[i][1];
            float4 f;
            f.x = fmaxf(v.f.x + b1v.x, 0.f);
            f.y = fmaxf(v.f.y + b1v.y, 0.f);
            f.z = fmaxf(v.f.z + b1v.z, 0.f);
            f.w = fmaxf(v.f.w + b1v.w, 0.f);
            *(float4*)&FS[(nb8 + i) * DFF + c1] = f;
        }
    }
    __syncthreads();

    {
        u64 acc[4][2];
#pragma unroll
        for (int i = 0; i < 4; i++) { acc[i][0] = 0ull; acc[i][1] = 0ull; }
#pragma unroll 2
        for (int k = 0; k < DFF; k += 2) {
            ulonglong2 w0 = *(const ulonglong2*)&W2[k * D + col];
            ulonglong2 w1 = *(const ulonglong2*)&W2[(k + 1) * D + col];
#pragma unroll
            for (int i = 0; i < 4; i++) {
                float2 fk = *(const float2*)&FS[(nb4 + i) * DFF + k];
                u64 d0 = dup2(fk.x), d1 = dup2(fk.y);
                acc[i][0] = ffma2(d0, w0.x, acc[i][0]);
                acc[i][1] = ffma2(d0, w0.y, acc[i][1]);
                acc[i][0] = ffma2(d1, w1.x, acc[i][0]);
                acc[i][1] = ffma2(d1, w1.y, acc[i][1]);
            }
        }
        __syncthreads();
        float4 b2v = *(const float4*)&b2[col];
#pragma unroll
        for (int i = 0; i < 4; i++) {
            float4 x = *(float4*)&XS[(nb4 + i) * D + col];
            V4 v; v.p[0] = acc[i][0]; v.p[1] = acc[i][1];
            x.x += v.f.x + b2v.x;
            x.y += v.f.y + b2v.y;
            x.z += v.f.z + b2v.z;
            x.w += v.f.w + b2v.w;
            *(float4*)&XS[(nb4 + i) * D + col] = x;
        }
    }
    __syncthreads();

    warp_ln4(XS, ln2g, ln2b, out + (long)n0 * D, t);
}

// ---------------- launch ----------------------------------------------------
extern "C" void kernel_launch(void* const* d_in, const int* in_sizes, int n_in,
                              void* d_out, int out_size)
{
    const float* h    = (const float*)d_in[0];
    const int*   src  = (const int*)  d_in[1];
    const int*   dst  = (const int*)  d_in[2];
    const float* Wq   = (const float*)d_in[3];
    const float* Wk   = (const float*)d_in[4];
    const float* Wv   = (const float*)d_in[5];
    const float* Wo   = (const float*)d_in[6];
    const float* bo   = (const float*)d_in[7];
    const float* ln1g = (const float*)d_in[8];
    const float* ln1b = (const float*)d_in[9];
    const float* W1   = (const float*)d_in[10];
    const float* b1   = (const float*)d_in[11];
    const float* W2   = (const float*)d_in[12];
    const float* b2   = (const float*)d_in[13];
    const float* ln2g = (const float*)d_in[14];
    const float* ln2b = (const float*)d_in[15];
    float* out = (float*)d_out;

    cudaFuncSetAttribute(qkv_mma_kernel,
                         cudaFuncAttributeMaxDynamicSharedMemorySize, QKV_SMEM);

    dim3 bgrid(64, 3);
    bprep_kernel<<<bgrid, 256>>>(Wq, Wk, Wv);
    zero_cnt_kernel<<<(N_NODES + 255) / 256, 256>>>();
    scatter_kernel<<<N_EDGES / 256, 256>>>(src, dst);
    qkv_mma_kernel<<<(N_NODES + 127) / 128, 256, QKV_SMEM>>>(h);
    agg_kernel<<<N_NODES / 8, 256>>>();
    epi_kernel<<<N_NODES / 32, 256>>>(h, Wo, bo, ln1g, ln1b,
                                      W1, b1, W2, b2, ln2g, ln2b, out);
}

// round 10
// speedup vs baseline: 2.6597x; 1.2231x over previous
#include <cuda_runtime.h>
#include <cuda_bf16.h>
#include <cstdint>

#define N_NODES 100000
#define N_EDGES 1600000
#define D 128
#define H 8
#define DH 16
#define DFF 256
#define CAP 96

// ---------------- scratch (device globals; no allocation allowed) ----------
__device__ float g_Q[N_NODES * D];
__device__ float g_KV[(long)N_NODES * 2 * D];   // [node][K 0..127 | V 128..255]
__device__ float g_wV[N_NODES * D];
__device__ float g_z[N_NODES * H];
__device__ int   g_cnt[N_NODES];
__device__ int   g_csr[(long)N_NODES * CAP];

// bf16 hi/lo weight images (row-major [k][c], exactly the MMA B operand)
__device__ __nv_bfloat16 g_Bh[3 * 16384],  g_Bl[3 * 16384];   // Wq,Wk,Wv
__device__ __nv_bfloat16 g_Woh[16384],     g_Wol[16384];
__device__ __nv_bfloat16 g_W1h[32768],     g_W1l[32768];
__device__ __nv_bfloat16 g_W2h[32768],     g_W2l[32768];

// ---------------- mma.sync helpers ------------------------------------------
__device__ __forceinline__ uint32_t smem_u32(const void* p) {
    uint32_t a;
    asm("{ .reg .u64 t; cvta.to.shared.u64 t, %1; cvt.u32.u64 %0, t; }"
        : "=r"(a) : "l"(p));
    return a;
}
__device__ __forceinline__ void ldsm_x4(uint32_t* r, uint32_t addr) {
    asm volatile("ldmatrix.sync.aligned.m8n8.x4.shared.b16 {%0,%1,%2,%3}, [%4];"
                 : "=r"(r[0]), "=r"(r[1]), "=r"(r[2]), "=r"(r[3]) : "r"(addr));
}
__device__ __forceinline__ void ldsm_x4_t(uint32_t* r, uint32_t addr) {
    asm volatile("ldmatrix.sync.aligned.m8n8.x4.trans.shared.b16 {%0,%1,%2,%3}, [%4];"
                 : "=r"(r[0]), "=r"(r[1]), "=r"(r[2]), "=r"(r[3]) : "r"(addr));
}
__device__ __forceinline__ void mma_bf16(float* d, const uint32_t* a,
                                         uint32_t b0, uint32_t b1) {
    asm volatile(
        "mma.sync.aligned.m16n8k16.row.col.f32.bf16.bf16.f32 "
        "{%0,%1,%2,%3}, {%4,%5,%6,%7}, {%8,%9}, {%0,%1,%2,%3};"
        : "+f"(d[0]), "+f"(d[1]), "+f"(d[2]), "+f"(d[3])
        : "r"(a[0]), "r"(a[1]), "r"(a[2]), "r"(a[3]), "r"(b0), "r"(b1));
}
__device__ __forceinline__ uint32_t pack2(__nv_bfloat16 a, __nv_bfloat16 b) {
    __nv_bfloat162 t; t.x = a; t.y = b;
    return *reinterpret_cast<uint32_t*>(&t);
}
__device__ __forceinline__ void cvt_hilo4(float4 v, uint2& hu, uint2& lu) {
    __nv_bfloat16 hx = __float2bfloat16(v.x), hy = __float2bfloat16(v.y);
    __nv_bfloat16 hz = __float2bfloat16(v.z), hw = __float2bfloat16(v.w);
    hu.x = pack2(hx, hy); hu.y = pack2(hz, hw);
    lu.x = pack2(__float2bfloat16(v.x - __bfloat162float(hx)),
                 __float2bfloat16(v.y - __bfloat162float(hy)));
    lu.y = pack2(__float2bfloat16(v.z - __bfloat162float(hz)),
                 __float2bfloat16(v.w - __bfloat162float(hw)));
}
__device__ __forceinline__ void cvt_hilo2(float a, float b, uint32_t& hv, uint32_t& lv) {
    __nv_bfloat16 ha = __float2bfloat16(a), hb = __float2bfloat16(b);
    hv = pack2(ha, hb);
    lv = pack2(__float2bfloat16(a - __bfloat162float(ha)),
               __float2bfloat16(b - __bfloat162float(hb)));
}

// ---------------- weight prep: bf16 hi/lo of all 6 matrices ------------------
__global__ void bprep_kernel(
    const float* __restrict__ Wq, const float* __restrict__ Wk,
    const float* __restrict__ Wv, const float* __restrict__ Wo,
    const float* __restrict__ W1, const float* __restrict__ W2)
{
    int m = blockIdx.y;
    const float* W; __nv_bfloat16 *oh, *ol; int tot;
    switch (m) {
        case 0: W = Wq; oh = g_Bh;          ol = g_Bl;          tot = 16384; break;
        case 1: W = Wk; oh = g_Bh + 16384;  ol = g_Bl + 16384;  tot = 16384; break;
        case 2: W = Wv; oh = g_Bh + 32768;  ol = g_Bl + 32768;  tot = 16384; break;
        case 3: W = Wo; oh = g_Woh;         ol = g_Wol;         tot = 16384; break;
        case 4: W = W1; oh = g_W1h;         ol = g_W1l;         tot = 32768; break;
        default:W = W2; oh = g_W2h;         ol = g_W2l;         tot = 32768; break;
    }
    int idx = blockIdx.x * 256 + threadIdx.x;
    if (idx >= tot) return;
    float x = W[idx];
    __nv_bfloat16 hb = __float2bfloat16(x);
    oh[idx] = hb;
    ol[idx] = __float2bfloat16(x - __bfloat162float(hb));
}

// ---------------- QKV via mma.sync (round-9 verified, 127us) -----------------
#define ASTRIDE_B 272
#define PART_BYTES (128 * ASTRIDE_B)
#define QKV_SMEM (4 * PART_BYTES)

__global__ __launch_bounds__(256) void qkv_mma_kernel(const float* __restrict__ h)
{
    extern __shared__ char smem[];
    char* Ah = smem;
    char* Al = smem + PART_BYTES;
    char* Bh = smem + 2 * PART_BYTES;
    char* Bl = smem + 3 * PART_BYTES;

    int tid = threadIdx.x;
    int lane = tid & 31;
    int w = tid >> 5;
    int n0 = blockIdx.x * 128;

    {
        int r = tid >> 1;
        int half = tid & 1;
        int n = n0 + r;
        const float4* hp = (const float4*)(h + (long)n * D + half * 64);
        char* dh = Ah + r * ASTRIDE_B + half * 128;
        char* dl = Al + r * ASTRIDE_B + half * 128;
        bool ok = (n < N_NODES);
#pragma unroll
        for (int j = 0; j < 16; j++) {
            float4 v = ok ? hp[j] : make_float4(0.f, 0.f, 0.f, 0.f);
            uint2 hu, lu;
            cvt_hilo4(v, hu, lu);
            *(uint2*)(dh + j * 8) = hu;
            *(uint2*)(dl + j * 8) = lu;
        }
    }

    uint32_t AhU = smem_u32(Ah), AlU = smem_u32(Al);
    uint32_t BhU = smem_u32(Bh), BlU = smem_u32(Bl);

    int mbase = (w >> 2) * 64;
    int nbase = (w & 3) * 32;

#pragma unroll 1
    for (int m = 0; m < 3; m++) {
        __syncthreads();
        {
            const uint4* sh = (const uint4*)(g_Bh + m * 16384);
            const uint4* sl = (const uint4*)(g_Bl + m * 16384);
            for (int ch = tid; ch < 2048; ch += 256) {
                int row = ch >> 4, o = ch & 15;
                *(uint4*)(Bh + row * ASTRIDE_B + o * 16) = sh[ch];
                *(uint4*)(Bl + row * ASTRIDE_B + o * 16) = sl[ch];
            }
        }
        __syncthreads();

        float acc[4][4][4];
#pragma unroll
        for (int mt = 0; mt < 4; mt++)
#pragma unroll
            for (int nt = 0; nt < 4; nt++)
#pragma unroll
                for (int q = 0; q < 4; q++) acc[mt][nt][q] = 0.f;

#pragma unroll 1
        for (int pass = 0; pass < 3; pass++) {
            uint32_t Abase = (pass == 2) ? AlU : AhU;
            uint32_t Bbase = (pass == 1) ? BlU : BhU;
#pragma unroll 1
            for (int kt = 0; kt < 8; kt++) {
                uint32_t a[4][4];
#pragma unroll
                for (int mt = 0; mt < 4; mt++) {
                    uint32_t addr = Abase
                        + (mbase + mt * 16 + (lane & 15)) * ASTRIDE_B
                        + kt * 32 + (lane >> 4) * 16;
                    ldsm_x4(a[mt], addr);
                }
                int g = lane >> 3, r8 = lane & 7;
#pragma unroll
                for (int nt2 = 0; nt2 < 2; nt2++) {
                    uint32_t b[4];
                    uint32_t baddr = Bbase
                        + (kt * 16 + (g & 1) * 8 + r8) * ASTRIDE_B
                        + (nbase + nt2 * 16 + (g >> 1) * 8) * 2;
                    ldsm_x4_t(b, baddr);
#pragma unroll
                    for (int mt = 0; mt < 4; mt++) {
                        mma_bf16(acc[mt][nt2 * 2],     a[mt], b[0], b[1]);
                        mma_bf16(acc[mt][nt2 * 2 + 1], a[mt], b[2], b[3]);
                    }
                }
            }
        }

        float* base = (m == 0) ? g_Q : (m == 1) ? g_KV : g_KV + D;
        long stride = (m == 0) ? D : 2 * D;
        int gid = lane >> 2, q4 = lane & 3;
#pragma unroll
        for (int mt = 0; mt < 4; mt++)
#pragma unroll
            for (int nt = 0; nt < 4; nt++) {
                int row = n0 + mbase + mt * 16 + gid;
                int col = nbase + nt * 8 + q4 * 2;
                if (row < N_NODES)
                    *(float2*)&base[(long)row * stride + col] =
                        make_float2(acc[mt][nt][0], acc[mt][nt][1]);
                if (row + 8 < N_NODES)
                    *(float2*)&base[(long)(row + 8) * stride + col] =
                        make_float2(acc[mt][nt][2], acc[mt][nt][3]);
            }
    }
}

// ---------------- epilogue via mma.sync --------------------------------------
// 64-node tile per block. smem: X fp32 [64][132], actX h/l [64] stride 272B,
// actF h/l [64] stride 528B, B chunk h/l [128] stride 272B.
#define EPI_X    0
#define EPI_AXH  33792
#define EPI_AXL  51200
#define EPI_AFH  68608
#define EPI_AFL  102400
#define EPI_BH   136192
#define EPI_BL   171008
#define EPI_SMEM 205824

__device__ __forceinline__ void copy_bchunk(
    char* smem, const __nv_bfloat16* srcH, const __nv_bfloat16* srcL,
    int srcStride, int rowOff, int colOff, int tid)
{
    for (int ch = tid; ch < 2048; ch += 256) {
        int row = ch >> 4, o = ch & 15;
        long idx = (long)(rowOff + row) * srcStride + colOff + o * 8;
        *(uint4*)(smem + EPI_BH + row * 272 + o * 16) = *(const uint4*)(srcH + idx);
        *(uint4*)(smem + EPI_BL + row * 272 + o * 16) = *(const uint4*)(srcL + idx);
    }
}

// 3-pass hi/lo GEMM for m64 tile: per warp m32 (mt 2) x n32 (nt 4).
__device__ __forceinline__ void gemm3pass(
    uint32_t AhU, uint32_t AlU, int astride, int kOff,
    uint32_t BhU, uint32_t BlU,
    int mbase, int nbase, int lane, float acc[2][4][4])
{
#pragma unroll 1
    for (int pass = 0; pass < 3; pass++) {
        uint32_t Abase = (pass == 2) ? AlU : AhU;
        uint32_t Bbase = (pass == 1) ? BlU : BhU;
#pragma unroll 1
        for (int kt = 0; kt < 8; kt++) {
            uint32_t a[2][4];
#pragma unroll
            for (int mt = 0; mt < 2; mt++) {
                uint32_t addr = Abase
                    + (mbase + mt * 16 + (lane & 15)) * astride
                    + kOff + kt * 32 + (lane >> 4) * 16;
                ldsm_x4(a[mt], addr);
            }
            int g = lane >> 3, r8 = lane & 7;
#pragma unroll
            for (int nt2 = 0; nt2 < 2; nt2++) {
                uint32_t b[4];
                uint32_t baddr = Bbase
                    + (kt * 16 + (g & 1) * 8 + r8) * 272
                    + (nbase + nt2 * 16 + (g >> 1) * 8) * 2;
                ldsm_x4_t(b, baddr);
#pragma unroll
                for (int mt = 0; mt < 2; mt++) {
                    mma_bf16(acc[mt][nt2 * 2],     a[mt], b[0], b[1]);
                    mma_bf16(acc[mt][nt2 * 2 + 1], a[mt], b[2], b[3]);
                }
            }
        }
    }
}

__global__ __launch_bounds__(256) void epi_mma_kernel(
    const float* __restrict__ h,
    const float* __restrict__ bo,
    const float* __restrict__ ln1g, const float* __restrict__ ln1b,
    const float* __restrict__ b1,  const float* __restrict__ b2,
    const float* __restrict__ ln2g, const float* __restrict__ ln2b,
    float* __restrict__ out)
{
    extern __shared__ char smem[];
    float* X = (float*)(smem + EPI_X);              // stride 132 floats

    int tid = threadIdx.x;
    int lane = tid & 31;
    int w = tid >> 5;
    int n0 = blockIdx.x * 64;

    uint32_t aXh = smem_u32(smem + EPI_AXH), aXl = smem_u32(smem + EPI_AXL);
    uint32_t aFh = smem_u32(smem + EPI_AFH), aFl = smem_u32(smem + EPI_AFL);
    uint32_t BhU = smem_u32(smem + EPI_BH),  BlU = smem_u32(smem + EPI_BL);

    int mbase = (w >> 2) * 32;
    int nbase = (w & 3) * 32;
    int gid = lane >> 2, q4 = lane & 3;

    // ---- step 1: A = wV/(z+eps) -> actX hi/lo ----
    {
        int r = tid >> 2;           // 0..63
        int q = tid & 3;            // 32-col block
        int n = n0 + r;
        bool ok = (n < N_NODES);
        float inv0 = ok ? 1.f / (g_z[(long)n * H + q * 2]     + 1e-6f) : 0.f;
        float inv1 = ok ? 1.f / (g_z[(long)n * H + q * 2 + 1] + 1e-6f) : 0.f;
        const float4* src = (const float4*)&g_wV[(long)n * D + q * 32];
#pragma unroll
        for (int j = 0; j < 8; j++) {
            float4 v = ok ? src[j] : make_float4(0.f, 0.f, 0.f, 0.f);
            float iv = (j < 4) ? inv0 : inv1;
            v.x *= iv; v.y *= iv; v.z *= iv; v.w *= iv;
            uint2 hu, lu;
            cvt_hilo4(v, hu, lu);
            *(uint2*)(smem + EPI_AXH + r * 272 + q * 64 + j * 8) = hu;
            *(uint2*)(smem + EPI_AXL + r * 272 + q * 64 + j * 8) = lu;
        }
    }
    __syncthreads();

    // ---- GEMM1: X = h + A @ Wo + bo ----
    copy_bchunk(smem, g_Woh, g_Wol, 128, 0, 0, tid);
    __syncthreads();
    {
        float acc[2][4][4];
#pragma unroll
        for (int mt = 0; mt < 2; mt++)
#pragma unroll
            for (int nt = 0; nt < 4; nt++)
#pragma unroll
                for (int q = 0; q < 4; q++) acc[mt][nt][q] = 0.f;
        gemm3pass(aXh, aXl, 272, 0, BhU, BlU, mbase, nbase, lane, acc);
#pragma unroll
        for (int mt = 0; mt < 2; mt++)
#pragma unroll
            for (int nt = 0; nt < 4; nt++) {
                int r = mbase + mt * 16 + gid;
                int col = nbase + nt * 8 + q4 * 2;
                float2 bov = *(const float2*)&bo[col];
                int n = n0 + r;
                float2 h0 = (n < N_NODES)
                    ? *(const float2*)&h[(long)n * D + col] : make_float2(0.f, 0.f);
                float2 h1 = (n + 8 < N_NODES)
                    ? *(const float2*)&h[(long)(n + 8) * D + col] : make_float2(0.f, 0.f);
                *(float2*)&X[r * 132 + col] =
                    make_float2(h0.x + acc[mt][nt][0] + bov.x,
                                h0.y + acc[mt][nt][1] + bov.y);
                *(float2*)&X[(r + 8) * 132 + col] =
                    make_float2(h1.x + acc[mt][nt][2] + bov.x,
                                h1.y + acc[mt][nt][3] + bov.y);
            }
    }
    __syncthreads();

    // ---- LN1 on X (fp32) + convert to actX hi/lo ----
    {
        float4 gv = *(const float4*)&ln1g[lane * 4];
        float4 bv = *(const float4*)&ln1b[lane * 4];
#pragma unroll
        for (int i = 0; i < 8; i++) {
            int r = w * 8 + i;
            float4 v = *(float4*)&X[r * 132 + lane * 4];
            float s  = v.x + v.y + v.z + v.w;
            float sq = v.x * v.x + v.y * v.y + v.z * v.z + v.w * v.w;
#pragma unroll
            for (int off = 16; off >= 1; off >>= 1) {
                s  += __shfl_xor_sync(0xffffffff, s, off);
                sq += __shfl_xor_sync(0xffffffff, sq, off);
            }
            float mu  = s * (1.f / D);
            float var = sq * (1.f / D) - mu * mu;
            float rs  = rsqrtf(var + 1e-5f);
            float4 o;
            o.x = (v.x - mu) * rs * gv.x + bv.x;
            o.y = (v.y - mu) * rs * gv.y + bv.y;
            o.z = (v.z - mu) * rs * gv.z + bv.z;
            o.w = (v.w - mu) * rs * gv.w + bv.w;
            *(float4*)&X[r * 132 + lane * 4] = o;
            uint2 hu, lu;
            cvt_hilo4(o, hu, lu);
            *(uint2*)(smem + EPI_AXH + r * 272 + lane * 8) = hu;
            *(uint2*)(smem + EPI_AXL + r * 272 + lane * 8) = lu;
        }
    }

    // ---- GEMM2: F = relu(X @ W1 + b1), two 128-col halves -> actF hi/lo ----
#pragma unroll 1
    for (int cc = 0; cc < DFF; cc += 128) {
        __syncthreads();
        copy_bchunk(smem, g_W1h, g_W1l, DFF, 0, cc, tid);
        __syncthreads();
        float acc[2][4][4];
#pragma unroll
        for (int mt = 0; mt < 2; mt++)
#pragma unroll
            for (int nt = 0; nt < 4; nt++)
#pragma unroll
                for (int q = 0; q < 4; q++) acc[mt][nt][q] = 0.f;
        gemm3pass(aXh, aXl, 272, 0, BhU, BlU, mbase, nbase, lane, acc);
#pragma unroll
        for (int mt = 0; mt < 2; mt++)
#pragma unroll
            for (int nt = 0; nt < 4; nt++) {
                int r = mbase + mt * 16 + gid;
                int col = nbase + nt * 8 + q4 * 2;
                float2 b1v = *(const float2*)&b1[cc + col];
                float f0 = fmaxf(acc[mt][nt][0] + b1v.x, 0.f);
                float f1 = fmaxf(acc[mt][nt][1] + b1v.y, 0.f);
                float f2 = fmaxf(acc[mt][nt][2] + b1v.x, 0.f);
                float f3 = fmaxf(acc[mt][nt][3] + b1v.y, 0.f);
                uint32_t hv, lv;
                cvt_hilo2(f0, f1, hv, lv);
                *(uint32_t*)(smem + EPI_AFH + r * 528 + (cc + col) * 2) = hv;
                *(uint32_t*)(smem + EPI_AFL + r * 528 + (cc + col) * 2) = lv;
                cvt_hilo2(f2, f3, hv, lv);
                *(uint32_t*)(smem + EPI_AFH + (r + 8) * 528 + (cc + col) * 2) = hv;
                *(uint32_t*)(smem + EPI_AFL + (r + 8) * 528 + (cc + col) * 2) = lv;
            }
    }

    // ---- GEMM3: Y = X + F @ W2 + b2, K=256 in two chunks ----
    {
        float acc[2][4][4];
#pragma unroll
        for (int mt = 0; mt < 2; mt++)
#pragma unroll
            for (int nt = 0; nt < 4; nt++)
#pragma unroll
                for (int q = 0; q < 4; q++) acc[mt][nt][q] = 0.f;
#pragma unroll 1
        for (int kc = 0; kc < DFF; kc += 128) {
            __syncthreads();
            copy_bchunk(smem, g_W2h, g_W2l, D, kc, 0, tid);
            __syncthreads();
            gemm3pass(aFh, aFl, 528, kc * 2, BhU, BlU, mbase, nbase, lane, acc);
        }
#pragma unroll
        for (int mt = 0; mt < 2; mt++)
#pragma unroll
            for (int nt = 0; nt < 4; nt++) {
                int r = mbase + mt * 16 + gid;
                int col = nbase + nt * 8 + q4 * 2;
                float2 b2v = *(const float2*)&b2[col];
                float2 x0 = *(float2*)&X[r * 132 + col];
                float2 x1 = *(float2*)&X[(r + 8) * 132 + col];
                *(float2*)&X[r * 132 + col] =
                    make_float2(x0.x + acc[mt][nt][0] + b2v.x,
                                x0.y + acc[mt][nt][1] + b2v.y);
                *(float2*)&X[(r + 8) * 132 + col] =
                    make_float2(x1.x + acc[mt][nt][2] + b2v.x,
                                x1.y + acc[mt][nt][3] + b2v.y);
            }
    }
    __syncthreads();

    // ---- LN2 -> out ----
    {
        float4 gv = *(const float4*)&ln2g[lane * 4];
        float4 bv = *(const float4*)&ln2b[lane * 4];
#pragma unroll
        for (int i = 0; i < 8; i++) {
            int r = w * 8 + i;
            int n = n0 + r;
            float4 v = *(float4*)&X[r * 132 + lane * 4];
            float s  = v.x + v.y + v.z + v.w;
            float sq = v.x * v.x + v.y * v.y + v.z * v.z + v.w * v.w;
#pragma unroll
            for (int off = 16; off >= 1; off >>= 1) {
                s  += __shfl_xor_sync(0xffffffff, s, off);
                sq += __shfl_xor_sync(0xffffffff, sq, off);
            }
            float mu  = s * (1.f / D);
            float var = sq * (1.f / D) - mu * mu;
            float rs  = rsqrtf(var + 1e-5f);
            float4 o;
            o.x = (v.x - mu) * rs * gv.x + bv.x;
            o.y = (v.y - mu) * rs * gv.y + bv.y;
            o.z = (v.z - mu) * rs * gv.z + bv.z;
            o.w = (v.w - mu) * rs * gv.w + bv.w;
            if (n < N_NODES)
                *(float4*)&out[(long)n * D + lane * 4] = o;
        }
    }
}

// ---------------- zero / scatter --------------------------------------------
__global__ void zero_cnt_kernel() {
    int i = blockIdx.x * blockDim.x + threadIdx.x;
    if (i < N_NODES) g_cnt[i] = 0;
}
__global__ __launch_bounds__(256) void scatter_kernel(
    const int* __restrict__ src, const int* __restrict__ dst)
{
    int e = blockIdx.x * 256 + threadIdx.x;
    if (e >= N_EDGES) return;
    int d = dst[e];
    int pos = atomicAdd(&g_cnt[d], 1);
    if (pos < CAP) g_csr[(long)d * CAP + pos] = src[e];
}

// ---------------- aggregation: one warp per dst node ------------------------
__global__ __launch_bounds__(256) void agg_kernel()
{
    int n = blockIdx.x * 8 + (threadIdx.x >> 5);
    int lane = threadIdx.x & 31;

    float4 q = *(const float4*)&g_Q[(long)n * D + lane * 4];
    float4 acc = make_float4(0.f, 0.f, 0.f, 0.f);
    float accz = 0.f;

    int deg = g_cnt[n];
    if (deg > CAP) deg = CAP;
    const int* __restrict__ lst = &g_csr[(long)n * CAP];

    if (deg > 0) {
        int s = lst[0];
        const float* kvp = &g_KV[(long)s * 2 * D];
        float4 k = *(const float4*)&kvp[lane * 4];
        float4 v = *(const float4*)&kvp[D + lane * 4];
        for (int j = 0; j < deg; j++) {
            float4 kc = k, vc = v;
            if (j + 1 < deg) {
                int s2 = lst[j + 1];
                const float* kvp2 = &g_KV[(long)s2 * 2 * D];
                k = *(const float4*)&kvp2[lane * 4];
                v = *(const float4*)&kvp2[D + lane * 4];
            }
            float ps = kc.x * q.x + kc.y * q.y + kc.z * q.z + kc.w * q.w;
            ps += __shfl_xor_sync(0xffffffff, ps, 1);
            ps += __shfl_xor_sync(0xffffffff, ps, 2);
            float sc = __expf(fminf(fmaxf(ps * 0.25f, -5.f), 5.f));
            acc.x += sc * vc.x; acc.y += sc * vc.y;
            acc.z += sc * vc.z; acc.w += sc * vc.w;
            accz += sc;
        }
    }

    *(float4*)&g_wV[(long)n * D + lane * 4] = acc;
    if ((lane & 3) == 0) g_z[(long)n * H + (lane >> 2)] = accz;
}

// ---------------- launch ----------------------------------------------------
extern "C" void kernel_launch(void* const* d_in, const int* in_sizes, int n_in,
                              void* d_out, int out_size)
{
    const float* h    = (const float*)d_in[0];
    const int*   src  = (const int*)  d_in[1];
    const int*   dst  = (const int*)  d_in[2];
    const float* Wq   = (const float*)d_in[3];
    const float* Wk   = (const float*)d_in[4];
    const float* Wv   = (const float*)d_in[5];
    const float* Wo   = (const float*)d_in[6];
    const float* bo   = (const float*)d_in[7];
    const float* ln1g = (const float*)d_in[8];
    const float* ln1b = (const float*)d_in[9];
    const float* W1   = (const float*)d_in[10];
    const float* b1   = (const float*)d_in[11];
    const float* W2   = (const float*)d_in[12];
    const float* b2   = (const float*)d_in[13];
    const float* ln2g = (const float*)d_in[14];
    const float* ln2b = (const float*)d_in[15];
    float* out = (float*)d_out;

    cudaFuncSetAttribute(qkv_mma_kernel,
                         cudaFuncAttributeMaxDynamicSharedMemorySize, QKV_SMEM);
    cudaFuncSetAttribute(epi_mma_kernel,
                         cudaFuncAttributeMaxDynamicSharedMemorySize, EPI_SMEM);

    dim3 bgrid(128, 6);
    bprep_kernel<<<bgrid, 256>>>(Wq, Wk, Wv, Wo, W1, W2);
    zero_cnt_kernel<<<(N_NODES + 255) / 256, 256>>>();
    scatter_kernel<<<N_EDGES / 256, 256>>>(src, dst);
    qkv_mma_kernel<<<(N_NODES + 127) / 128, 256, QKV_SMEM>>>(h);
    agg_kernel<<<N_NODES / 8, 256>>>();
    epi_mma_kernel<<<(N_NODES + 63) / 64, 256, EPI_SMEM>>>(
        h, bo, ln1g, ln1b, b1, b2, ln2g, ln2b, out);
}